// round 1
// baseline (speedup 1.0000x reference)
#include <cuda_runtime.h>
#include <cuda_bf16.h>
#include <math.h>

// Shapes (fixed for this problem)
#define B_ 4
#define N_ 1024
#define D_ 1024
#define H_ 16
#define HD_ 64
#define M_ (B_ * N_)          // 4096 rows
#define QKV_ (3 * D_)         // 3072

// -------- scratch (no allocations allowed; __device__ globals) --------
__device__ float g_h[M_ * D_];        // SLN output
__device__ float g_qkv[M_ * QKV_];    // qkv projections
__device__ float g_attn[M_ * D_];     // attention output (B,N,H*hd)
__device__ float g_h1[M_ * D_];       // residual stream after attn proj
__device__ float g_gamma[B_ * D_];
__device__ float g_beta[B_ * D_];

// ===================================================================
// gamma/beta: out[b,d] = dot(w[b,:], W[d,:]) + bias[d]
// 8192 outputs, one thread each.
// ===================================================================
__global__ __launch_bounds__(256) void gamma_beta_kernel(
    const float* __restrict__ w,
    const float* __restrict__ Wg, const float* __restrict__ bg,
    const float* __restrict__ Wb, const float* __restrict__ bb)
{
    int idx = blockIdx.x * 256 + threadIdx.x;   // 0..8191
    int which = idx >> 12;
    int b = (idx >> 10) & 3;
    int d = idx & 1023;
    const float* Wrow = (which ? Wb : Wg) + (size_t)d * D_;
    const float* wr = w + b * D_;
    float acc = 0.f;
    #pragma unroll 4
    for (int k = 0; k < D_; k += 4) {
        float4 a = *(const float4*)&wr[k];
        float4 c = *(const float4*)&Wrow[k];
        acc += a.x * c.x + a.y * c.y + a.z * c.z + a.w * c.w;
    }
    if (which) g_beta[b * D_ + d]  = acc + bb[d];
    else       g_gamma[b * D_ + d] = acc + bg[d];
}

// ===================================================================
// SLN: out = gamma[b]*((x-mu)*rstd*ln_g + ln_b) + beta[b]  (+ x if add_res)
// one block per row (4096 rows), 256 threads, 4 elems/thread
// ===================================================================
__global__ __launch_bounds__(256) void sln_kernel(
    const float* __restrict__ x,
    const float* __restrict__ ln_g, const float* __restrict__ ln_b,
    float* __restrict__ out, int add_res)
{
    int row = blockIdx.x;
    int b = row >> 10;
    const float* xr = x + (size_t)row * D_;
    int t = threadIdx.x;

    float4 v = ((const float4*)xr)[t];
    float s  = v.x + v.y + v.z + v.w;
    float sq = v.x * v.x + v.y * v.y + v.z * v.z + v.w * v.w;
    #pragma unroll
    for (int o = 16; o; o >>= 1) {
        s  += __shfl_xor_sync(0xffffffffu, s, o);
        sq += __shfl_xor_sync(0xffffffffu, sq, o);
    }
    __shared__ float ss[8], ssq[8];
    int w = t >> 5, ln = t & 31;
    if (ln == 0) { ss[w] = s; ssq[w] = sq; }
    __syncthreads();
    s = 0.f; sq = 0.f;
    #pragma unroll
    for (int i = 0; i < 8; i++) { s += ss[i]; sq += ssq[i]; }

    float mu = s * (1.f / D_);
    float var = sq * (1.f / D_) - mu * mu;
    float rstd = rsqrtf(var + 1e-5f);

    float4 lg = ((const float4*)ln_g)[t];
    float4 lb = ((const float4*)ln_b)[t];
    float4 ga = ((const float4*)(g_gamma + b * D_))[t];
    float4 be = ((const float4*)(g_beta  + b * D_))[t];

    float4 r;
    r.x = ga.x * ((v.x - mu) * rstd * lg.x + lb.x) + be.x;
    r.y = ga.y * ((v.y - mu) * rstd * lg.y + lb.y) + be.y;
    r.z = ga.z * ((v.z - mu) * rstd * lg.z + lb.z) + be.z;
    r.w = ga.w * ((v.w - mu) * rstd * lg.w + lb.w) + be.w;
    if (add_res) { r.x += v.x; r.y += v.y; r.z += v.z; r.w += v.w; }
    ((float4*)(out + (size_t)row * D_))[t] = r;
}

// ===================================================================
// SGEMM: C[M,N] = A[M,K] @ W[N,K]^T + bias[N] (+ residual[M,N])
// 128x128x16 tiles, 256 threads, 8x8 per thread
// ===================================================================
#define BM 128
#define BN 128
#define BK 16

__global__ __launch_bounds__(256) void sgemm_bias(
    const float* __restrict__ A, const float* __restrict__ W,
    const float* __restrict__ bias, const float* __restrict__ residual,
    float* __restrict__ C, int M, int N, int K)
{
    __shared__ float As[BK][BM + 4];
    __shared__ float Bs[BK][BN + 4];
    int tid = threadIdx.x;
    int tx = tid & 15, ty = tid >> 4;
    int m0 = blockIdx.y * BM, n0 = blockIdx.x * BN;

    float acc[8][8] = {};

    for (int kk = 0; kk < K; kk += BK) {
        #pragma unroll
        for (int p = 0; p < 2; p++) {
            int j = tid + p * 256;       // 0..511
            int row = j >> 2;
            int kc = (j & 3) * 4;
            float4 av = *(const float4*)&A[(size_t)(m0 + row) * K + kk + kc];
            As[kc + 0][row] = av.x; As[kc + 1][row] = av.y;
            As[kc + 2][row] = av.z; As[kc + 3][row] = av.w;
            float4 bv = *(const float4*)&W[(size_t)(n0 + row) * K + kk + kc];
            Bs[kc + 0][row] = bv.x; Bs[kc + 1][row] = bv.y;
            Bs[kc + 2][row] = bv.z; Bs[kc + 3][row] = bv.w;
        }
        __syncthreads();
        #pragma unroll
        for (int k = 0; k < BK; k++) {
            float4 a0 = *(const float4*)&As[k][ty * 8];
            float4 a1 = *(const float4*)&As[k][ty * 8 + 4];
            float4 b0 = *(const float4*)&Bs[k][tx * 8];
            float4 b1 = *(const float4*)&Bs[k][tx * 8 + 4];
            float ar[8] = {a0.x, a0.y, a0.z, a0.w, a1.x, a1.y, a1.z, a1.w};
            float br[8] = {b0.x, b0.y, b0.z, b0.w, b1.x, b1.y, b1.z, b1.w};
            #pragma unroll
            for (int i = 0; i < 8; i++)
                #pragma unroll
                for (int j = 0; j < 8; j++)
                    acc[i][j] += ar[i] * br[j];
        }
        __syncthreads();
    }

    #pragma unroll
    for (int i = 0; i < 8; i++) {
        int m = m0 + ty * 8 + i;
        #pragma unroll
        for (int jj = 0; jj < 8; jj += 4) {
            int n = n0 + tx * 8 + jj;
            float4 r;
            r.x = acc[i][jj + 0] + bias[n + 0];
            r.y = acc[i][jj + 1] + bias[n + 1];
            r.z = acc[i][jj + 2] + bias[n + 2];
            r.w = acc[i][jj + 3] + bias[n + 3];
            if (residual) {
                float4 rv = *(const float4*)&residual[(size_t)m * N + n];
                r.x += rv.x; r.y += rv.y; r.z += rv.z; r.w += rv.w;
            }
            *(float4*)&C[(size_t)m * N + n] = r;
        }
    }
}

// ===================================================================
// Flash attention, fp32. One block per (b,h,qtile of 64).
// qkv layout col = h*192 + d*3 + {0,1,2}. att = softmax(QK^T)/32 @ V.
// ===================================================================
#define FL_PAD 68
#define FLASH_SMEM (4 * 64 * FL_PAD * 4)

__global__ __launch_bounds__(256) void flash_kernel(float* __restrict__ outp)
{
    extern __shared__ float sm[];
    float* Qs = sm;                 // [d][q]
    float* Ks = sm + 64 * FL_PAD;   // [d][k]
    float* Vs = sm + 2 * 64 * FL_PAD; // [k][d]
    float* Ps = sm + 3 * 64 * FL_PAD; // [k][q]

    int tid = threadIdx.x;
    int bh = blockIdx.y;
    int b = bh >> 4, h = bh & 15;
    int q0 = blockIdx.x * 64;
    size_t base = (size_t)b * N_ * QKV_ + (size_t)h * 192;
    const float* qkv = g_qkv;

    // load Q tile transposed [d][q]
    #pragma unroll
    for (int it = 0; it < 16; it++) {
        int i = it * 256 + tid;
        int q = i >> 6, d = i & 63;
        Qs[d * FL_PAD + q] = qkv[base + (size_t)(q0 + q) * QKV_ + d * 3];
    }

    int tq = (tid >> 4) * 4;
    int tk = (tid & 15) * 4;
    float m[4] = {-1e30f, -1e30f, -1e30f, -1e30f};
    float l[4] = {0.f, 0.f, 0.f, 0.f};
    float o[4][4] = {};

    for (int n0 = 0; n0 < N_; n0 += 64) {
        #pragma unroll
        for (int it = 0; it < 16; it++) {
            int i = it * 256 + tid;
            int r = i >> 6, d = i & 63;
            size_t p = base + (size_t)(n0 + r) * QKV_ + d * 3;
            Ks[d * FL_PAD + r] = qkv[p + 1];
            Vs[r * FL_PAD + d] = qkv[p + 2];
        }
        __syncthreads();

        // S = Q K^T (4x4 per thread)
        float s[4][4] = {};
        #pragma unroll
        for (int d = 0; d < 64; d++) {
            float4 a = *(const float4*)&Qs[d * FL_PAD + tq];
            float4 bb4 = *(const float4*)&Ks[d * FL_PAD + tk];
            float ar[4] = {a.x, a.y, a.z, a.w};
            float br[4] = {bb4.x, bb4.y, bb4.z, bb4.w};
            #pragma unroll
            for (int i = 0; i < 4; i++)
                #pragma unroll
                for (int j = 0; j < 4; j++)
                    s[i][j] += ar[i] * br[j];
        }

        // online softmax per q-row (row group = 16 lanes sharing tid>>4)
        #pragma unroll
        for (int i = 0; i < 4; i++) {
            float rm = fmaxf(fmaxf(s[i][0], s[i][1]), fmaxf(s[i][2], s[i][3]));
            #pragma unroll
            for (int off = 1; off < 16; off <<= 1)
                rm = fmaxf(rm, __shfl_xor_sync(0xffffffffu, rm, off));
            float mn = fmaxf(m[i], rm);
            float corr = __expf(m[i] - mn);
            float rs = 0.f;
            #pragma unroll
            for (int j = 0; j < 4; j++) {
                s[i][j] = __expf(s[i][j] - mn);
                rs += s[i][j];
            }
            #pragma unroll
            for (int off = 1; off < 16; off <<= 1)
                rs += __shfl_xor_sync(0xffffffffu, rs, off);
            l[i] = l[i] * corr + rs;
            m[i] = mn;
            #pragma unroll
            for (int j = 0; j < 4; j++) o[i][j] *= corr;
            #pragma unroll
            for (int j = 0; j < 4; j++)
                Ps[(tk + j) * FL_PAD + tq + i] = s[i][j];
        }
        __syncthreads();

        // O += P @ V  (thread's d-range == tk range)
        #pragma unroll
        for (int k = 0; k < 64; k++) {
            float4 a = *(const float4*)&Ps[k * FL_PAD + tq];
            float4 v4 = *(const float4*)&Vs[k * FL_PAD + tk];
            float ar[4] = {a.x, a.y, a.z, a.w};
            float vr[4] = {v4.x, v4.y, v4.z, v4.w};
            #pragma unroll
            for (int i = 0; i < 4; i++)
                #pragma unroll
                for (int j = 0; j < 4; j++)
                    o[i][j] += ar[i] * vr[j];
        }
        __syncthreads();
    }

    // normalize (softmax denom and the /sqrt(D)=32 quirk) and store
    #pragma unroll
    for (int i = 0; i < 4; i++) {
        float inv = 1.f / (l[i] * 32.0f);
        float4 r;
        r.x = o[i][0] * inv; r.y = o[i][1] * inv;
        r.z = o[i][2] * inv; r.w = o[i][3] * inv;
        size_t off = ((size_t)(b * N_ + q0 + tq + i)) * D_ + h * HD_ + tk;
        *(float4*)&outp[off] = r;
    }
}

// ===================================================================
extern "C" void kernel_launch(void* const* d_in, const int* in_sizes, int n_in,
                              void* d_out, int out_size)
{
    const float* hidden = (const float*)d_in[0];
    const float* w      = (const float*)d_in[1];
    const float* ln_g   = (const float*)d_in[2];
    const float* ln_b   = (const float*)d_in[3];
    const float* Wg     = (const float*)d_in[4];
    const float* bg     = (const float*)d_in[5];
    const float* Wb     = (const float*)d_in[6];
    const float* bb     = (const float*)d_in[7];
    const float* Wqkv   = (const float*)d_in[8];
    const float* bqkv   = (const float*)d_in[9];
    const float* Wp     = (const float*)d_in[10];
    const float* bp     = (const float*)d_in[11];
    float* out = (float*)d_out;

    float *p_h, *p_qkv, *p_attn, *p_h1;
    cudaGetSymbolAddress((void**)&p_h, g_h);
    cudaGetSymbolAddress((void**)&p_qkv, g_qkv);
    cudaGetSymbolAddress((void**)&p_attn, g_attn);
    cudaGetSymbolAddress((void**)&p_h1, g_h1);

    cudaFuncSetAttribute(flash_kernel,
                         cudaFuncAttributeMaxDynamicSharedMemorySize, FLASH_SMEM);

    // 1) gamma/beta
    gamma_beta_kernel<<<32, 256>>>(w, Wg, bg, Wb, bb);

    // 2) h = sln(hidden)
    sln_kernel<<<M_, 256>>>(hidden, ln_g, ln_b, p_h, 0);

    // 3) qkv = h @ Wqkv^T + bqkv
    sgemm_bias<<<dim3(QKV_ / BN, M_ / BM), 256>>>(p_h, Wqkv, bqkv, nullptr,
                                                  p_qkv, M_, QKV_, D_);

    // 4) attention
    flash_kernel<<<dim3(N_ / 64, B_ * H_), 256, FLASH_SMEM>>>(p_attn);

    // 5) h1 = attn @ Wp^T + bp + hidden
    sgemm_bias<<<dim3(D_ / BN, M_ / BM), 256>>>(p_attn, Wp, bp, hidden,
                                                p_h1, M_, D_, D_);

    // 6) out = sln(h1) + h1
    sln_kernel<<<M_, 256>>>(p_h1, ln_g, ln_b, out, 1);
}

// round 3
// speedup vs baseline: 1.4253x; 1.4253x over previous
#include <cuda_runtime.h>
#include <cuda_bf16.h>
#include <math.h>
#include <stdint.h>

// Shapes (fixed for this problem)
#define B_ 4
#define N_ 1024
#define D_ 1024
#define H_ 16
#define HD_ 64
#define M_ (B_ * N_)          // 4096 rows
#define QKV_ (3 * D_)         // 3072

// -------- scratch (no allocations allowed; __device__ globals) --------
__device__ float g_h[M_ * D_];        // SLN output
__device__ float g_qkv[M_ * QKV_];    // qkv projections
__device__ float g_attn[M_ * D_];     // attention output
__device__ float g_h1[M_ * D_];       // residual stream after attn proj
__device__ float g_gamma[B_ * D_];
__device__ float g_beta[B_ * D_];
// bf16 split buffers
__device__ __nv_bfloat16 g_Ahi[M_ * D_];
__device__ __nv_bfloat16 g_Alo[M_ * D_];
__device__ __nv_bfloat16 g_Bhi[QKV_ * D_];
__device__ __nv_bfloat16 g_Blo[QKV_ * D_];

__device__ __forceinline__ uint32_t smem_to_u32(const void* p) {
    uint32_t a;
    asm("{ .reg .u64 t; cvta.to.shared.u64 t, %1; cvt.u32.u64 %0, t; }"
        : "=r"(a) : "l"(p));
    return a;
}

// ===================================================================
// gamma/beta: out[b,d] = dot(w[b,:], W[d,:]) + bias[d]
// ===================================================================
__global__ __launch_bounds__(256) void gamma_beta_kernel(
    const float* __restrict__ w,
    const float* __restrict__ Wg, const float* __restrict__ bg,
    const float* __restrict__ Wb, const float* __restrict__ bb)
{
    int idx = blockIdx.x * 256 + threadIdx.x;
    int which = idx >> 12;
    int b = (idx >> 10) & 3;
    int d = idx & 1023;
    const float* Wrow = (which ? Wb : Wg) + (size_t)d * D_;
    const float* wr = w + b * D_;
    float acc = 0.f;
    #pragma unroll 4
    for (int k = 0; k < D_; k += 4) {
        float4 a = *(const float4*)&wr[k];
        float4 c = *(const float4*)&Wrow[k];
        acc += a.x * c.x + a.y * c.y + a.z * c.z + a.w * c.w;
    }
    if (which) g_beta[b * D_ + d]  = acc + bb[d];
    else       g_gamma[b * D_ + d] = acc + bg[d];
}

// ===================================================================
// SLN: out = gamma[b]*((x-mu)*rstd*ln_g + ln_b) + beta[b]  (+ x)
// ===================================================================
__global__ __launch_bounds__(256) void sln_kernel(
    const float* __restrict__ x,
    const float* __restrict__ ln_g, const float* __restrict__ ln_b,
    float* __restrict__ out, int add_res)
{
    int row = blockIdx.x;
    int b = row >> 10;
    const float* xr = x + (size_t)row * D_;
    int t = threadIdx.x;

    float4 v = ((const float4*)xr)[t];
    float s  = v.x + v.y + v.z + v.w;
    float sq = v.x * v.x + v.y * v.y + v.z * v.z + v.w * v.w;
    #pragma unroll
    for (int o = 16; o; o >>= 1) {
        s  += __shfl_xor_sync(0xffffffffu, s, o);
        sq += __shfl_xor_sync(0xffffffffu, sq, o);
    }
    __shared__ float ss[8], ssq[8];
    int w = t >> 5, ln = t & 31;
    if (ln == 0) { ss[w] = s; ssq[w] = sq; }
    __syncthreads();
    s = 0.f; sq = 0.f;
    #pragma unroll
    for (int i = 0; i < 8; i++) { s += ss[i]; sq += ssq[i]; }

    float mu = s * (1.f / D_);
    float var = sq * (1.f / D_) - mu * mu;
    float rstd = rsqrtf(var + 1e-5f);

    float4 lg = ((const float4*)ln_g)[t];
    float4 lb = ((const float4*)ln_b)[t];
    float4 ga = ((const float4*)(g_gamma + b * D_))[t];
    float4 be = ((const float4*)(g_beta  + b * D_))[t];

    float4 r;
    r.x = ga.x * ((v.x - mu) * rstd * lg.x + lb.x) + be.x;
    r.y = ga.y * ((v.y - mu) * rstd * lg.y + lb.y) + be.y;
    r.z = ga.z * ((v.z - mu) * rstd * lg.z + lb.z) + be.z;
    r.w = ga.w * ((v.w - mu) * rstd * lg.w + lb.w) + be.w;
    if (add_res) { r.x += v.x; r.y += v.y; r.z += v.z; r.w += v.w; }
    ((float4*)(out + (size_t)row * D_))[t] = r;
}

// ===================================================================
// split fp32 -> (hi, lo) bf16 pair
// ===================================================================
__device__ __forceinline__ uint32_t split_pair(float f0, float f1, uint32_t& lo) {
    __nv_bfloat16 h0 = __float2bfloat16_rn(f0);
    __nv_bfloat16 h1 = __float2bfloat16_rn(f1);
    __nv_bfloat16 l0 = __float2bfloat16_rn(f0 - __bfloat162float(h0));
    __nv_bfloat16 l1 = __float2bfloat16_rn(f1 - __bfloat162float(h1));
    lo = (uint32_t)__bfloat16_as_ushort(l0) | ((uint32_t)__bfloat16_as_ushort(l1) << 16);
    return (uint32_t)__bfloat16_as_ushort(h0) | ((uint32_t)__bfloat16_as_ushort(h1) << 16);
}

__global__ __launch_bounds__(256) void cvt_split(
    const float* __restrict__ src,
    __nv_bfloat16* __restrict__ hi, __nv_bfloat16* __restrict__ lo)
{
    int i = (blockIdx.x * 256 + threadIdx.x) * 8;
    float4 a = *(const float4*)(src + i);
    float4 b = *(const float4*)(src + i + 4);
    uint4 vh, vl;
    vh.x = split_pair(a.x, a.y, vl.x);
    vh.y = split_pair(a.z, a.w, vl.y);
    vh.z = split_pair(b.x, b.y, vl.z);
    vh.w = split_pair(b.z, b.w, vl.w);
    *(uint4*)(hi + i) = vh;
    *(uint4*)(lo + i) = vl;
}

// ===================================================================
// mma.sync bf16 GEMM: C[M,N] = A[M,K] @ W[N,K]^T + bias (+residual)
// split-bf16 3-term. CTA 128x128, BK=32, 8 warps (2x4), double-buffered.
// ===================================================================
#define RS 40                       // smem row stride in bf16 (32 + 8 pad)
#define MAT_ELEMS (128 * RS)        // per-matrix tile elements
#define STAGE_ELEMS (4 * MAT_ELEMS) // Ahi,Alo,Bhi,Blo
#define GEMM_SMEM (2 * STAGE_ELEMS * 2)  // bytes (2 stages, bf16)

__device__ __forceinline__ void ldmx4(uint32_t* r, uint32_t addr) {
    asm volatile("ldmatrix.sync.aligned.m8n8.x4.shared.b16 {%0,%1,%2,%3}, [%4];"
                 : "=r"(r[0]), "=r"(r[1]), "=r"(r[2]), "=r"(r[3]) : "r"(addr));
}
__device__ __forceinline__ void ldmx2(uint32_t* r, uint32_t addr) {
    asm volatile("ldmatrix.sync.aligned.m8n8.x2.shared.b16 {%0,%1}, [%2];"
                 : "=r"(r[0]), "=r"(r[1]) : "r"(addr));
}
__device__ __forceinline__ void mma16816(float* c, const uint32_t* a, const uint32_t* b) {
    asm volatile("mma.sync.aligned.m16n8k16.row.col.f32.bf16.bf16.f32 "
                 "{%0,%1,%2,%3}, {%4,%5,%6,%7}, {%8,%9}, {%0,%1,%2,%3};"
                 : "+f"(c[0]), "+f"(c[1]), "+f"(c[2]), "+f"(c[3])
                 : "r"(a[0]), "r"(a[1]), "r"(a[2]), "r"(a[3]), "r"(b[0]), "r"(b[1]));
}

__global__ __launch_bounds__(256) void gemm_mma(
    const __nv_bfloat16* __restrict__ Ahi, const __nv_bfloat16* __restrict__ Alo,
    const __nv_bfloat16* __restrict__ Bhi, const __nv_bfloat16* __restrict__ Blo,
    const float* __restrict__ bias, const float* __restrict__ residual,
    float* __restrict__ C, int M, int N, int K)
{
    extern __shared__ __nv_bfloat16 smb[];
    uint32_t sbase = smem_to_u32(smb);
    int tid = threadIdx.x, wid = tid >> 5, lane = tid & 31;
    int m0 = blockIdx.y * 128, n0 = blockIdx.x * 128;
    int wm = wid >> 2, wn = wid & 3;

    float acc[4][4][4];
    #pragma unroll
    for (int i = 0; i < 4; i++)
        #pragma unroll
        for (int j = 0; j < 4; j++)
            #pragma unroll
            for (int c = 0; c < 4; c++) acc[i][j][c] = 0.f;

    const int nch = K >> 5;

    auto load_stage = [&](int ch, int s) {
        int kk = ch << 5;
        #pragma unroll
        for (int t = 0; t < 8; t++) {
            int idx = t * 256 + tid;        // 0..2047
            int mat = idx >> 9;             // 0..3
            int row = (idx >> 2) & 127;
            int seg = idx & 3;
            const __nv_bfloat16* src = (mat == 0) ? Ahi : (mat == 1) ? Alo
                                     : (mat == 2) ? Bhi : Blo;
            int rb = (mat < 2) ? m0 : n0;
            const __nv_bfloat16* g = src + (size_t)(rb + row) * K + kk + seg * 8;
            uint32_t dst = sbase + (uint32_t)((s * STAGE_ELEMS + mat * MAT_ELEMS
                                               + row * RS + seg * 8) * 2);
            asm volatile("cp.async.cg.shared.global [%0], [%1], 16;"
                         :: "r"(dst), "l"(g) : "memory");
        }
        asm volatile("cp.async.commit_group;" ::: "memory");
    };

    auto compute_stage = [&](int s) {
        uint32_t stage_b = sbase + (uint32_t)(s * STAGE_ELEMS * 2);
        #pragma unroll
        for (int ks = 0; ks < 2; ks++) {
            uint32_t ahi[4][4], alo[4][4];
            int arow = wm * 64 + (lane & 15);
            int acol = ks * 16 + (lane >> 4) * 8;
            #pragma unroll
            for (int i = 0; i < 4; i++) {
                uint32_t off = (uint32_t)(((arow + i * 16) * RS + acol) * 2);
                ldmx4(ahi[i], stage_b + 0 * MAT_ELEMS * 2 + off);
                ldmx4(alo[i], stage_b + 1 * MAT_ELEMS * 2 + off);
            }
            uint32_t bhi[4][2], blo[4][2];
            int bl = lane & 15;
            int brow = wn * 32 + (bl & 7);
            int bcol = ks * 16 + (bl >> 3) * 8;
            #pragma unroll
            for (int j = 0; j < 4; j++) {
                uint32_t off = (uint32_t)(((brow + j * 8) * RS + bcol) * 2);
                ldmx2(bhi[j], stage_b + 2 * MAT_ELEMS * 2 + off);
                ldmx2(blo[j], stage_b + 3 * MAT_ELEMS * 2 + off);
            }
            #pragma unroll
            for (int i = 0; i < 4; i++)
                #pragma unroll
                for (int j = 0; j < 4; j++) {
                    mma16816(acc[i][j], ahi[i], bhi[j]);
                    mma16816(acc[i][j], ahi[i], blo[j]);
                    mma16816(acc[i][j], alo[i], bhi[j]);
                }
        }
    };

    load_stage(0, 0);
    for (int ch = 0; ch < nch; ch++) {
        if (ch + 1 < nch) {
            load_stage(ch + 1, (ch + 1) & 1);
            asm volatile("cp.async.wait_group 1;" ::: "memory");
        } else {
            asm volatile("cp.async.wait_group 0;" ::: "memory");
        }
        __syncthreads();
        compute_stage(ch & 1);
        __syncthreads();
    }

    // epilogue
    int r = lane >> 2, cp2 = (lane & 3) * 2;
    #pragma unroll
    for (int i = 0; i < 4; i++) {
        int row0 = m0 + wm * 64 + i * 16 + r;
        #pragma unroll
        for (int j = 0; j < 4; j++) {
            int col = n0 + wn * 32 + j * 8 + cp2;
            float2 bv = *(const float2*)(bias + col);
            float2 o0, o1;
            o0.x = acc[i][j][0] + bv.x; o0.y = acc[i][j][1] + bv.y;
            o1.x = acc[i][j][2] + bv.x; o1.y = acc[i][j][3] + bv.y;
            if (residual) {
                float2 r0 = *(const float2*)(residual + (size_t)row0 * N + col);
                float2 r1 = *(const float2*)(residual + (size_t)(row0 + 8) * N + col);
                o0.x += r0.x; o0.y += r0.y;
                o1.x += r1.x; o1.y += r1.y;
            }
            *(float2*)(C + (size_t)row0 * N + col) = o0;
            *(float2*)(C + (size_t)(row0 + 8) * N + col) = o1;
        }
    }
}

// ===================================================================
// Flash attention fp32 SIMT, q-tile 128 x k-tile 64, 8x4 per thread.
// ===================================================================
#define PQ 132
#define PK 68
#define FLASH_SMEM (64 * (PQ + PK + PK + PQ) * 4)   // 102400 B

__global__ __launch_bounds__(256) void flash_kernel(float* __restrict__ outp)
{
    extern __shared__ float smf[];
    float* Qs = smf;                       // [d][q] 64 x PQ
    float* Ks = Qs + 64 * PQ;              // [d][k] 64 x PK
    float* Vs = Ks + 64 * PK;              // [k][d] 64 x PK
    float* Ps = Vs + 64 * PK;              // [k][q] 64 x PQ

    int tid = threadIdx.x;
    int bh = blockIdx.y;
    int b = bh >> 4, h = bh & 15;
    int q0 = blockIdx.x * 128;
    size_t bas = (size_t)b * N_ * QKV_ + (size_t)h * 192;
    const float* qkv = g_qkv;

    #pragma unroll
    for (int it = 0; it < 32; it++) {
        int i = it * 256 + tid;
        int q = i >> 6, d = i & 63;
        Qs[d * PQ + q] = qkv[bas + (size_t)(q0 + q) * QKV_ + d * 3];
    }

    int ty = tid >> 4, tx = tid & 15;
    int tq = ty * 8, tk = tx * 4;
    float m[8], l[8];
    #pragma unroll
    for (int i = 0; i < 8; i++) { m[i] = -1e30f; l[i] = 0.f; }
    float o[8][4] = {};

    for (int n0 = 0; n0 < N_; n0 += 64) {
        #pragma unroll
        for (int it = 0; it < 16; it++) {
            int i = it * 256 + tid;
            int rr = i >> 6, d = i & 63;
            size_t p = bas + (size_t)(n0 + rr) * QKV_ + d * 3;
            Ks[d * PK + rr] = qkv[p + 1];
            Vs[rr * PK + d] = qkv[p + 2];
        }
        __syncthreads();

        float s[8][4] = {};
        #pragma unroll
        for (int d = 0; d < 64; d++) {
            float4 a0 = *(const float4*)&Qs[d * PQ + tq];
            float4 a1 = *(const float4*)&Qs[d * PQ + tq + 4];
            float4 bv = *(const float4*)&Ks[d * PK + tk];
            float ar[8] = {a0.x, a0.y, a0.z, a0.w, a1.x, a1.y, a1.z, a1.w};
            float br[4] = {bv.x, bv.y, bv.z, bv.w};
            #pragma unroll
            for (int i = 0; i < 8; i++)
                #pragma unroll
                for (int j = 0; j < 4; j++)
                    s[i][j] += ar[i] * br[j];
        }

        #pragma unroll
        for (int i = 0; i < 8; i++) {
            float rm = fmaxf(fmaxf(s[i][0], s[i][1]), fmaxf(s[i][2], s[i][3]));
            #pragma unroll
            for (int off = 1; off < 16; off <<= 1)
                rm = fmaxf(rm, __shfl_xor_sync(0xffffffffu, rm, off));
            float mn = fmaxf(m[i], rm);
            float corr = __expf(m[i] - mn);
            float rs = 0.f;
            #pragma unroll
            for (int j = 0; j < 4; j++) {
                s[i][j] = __expf(s[i][j] - mn);
                rs += s[i][j];
            }
            #pragma unroll
            for (int off = 1; off < 16; off <<= 1)
                rs += __shfl_xor_sync(0xffffffffu, rs, off);
            l[i] = l[i] * corr + rs;
            m[i] = mn;
            #pragma unroll
            for (int j = 0; j < 4; j++) o[i][j] *= corr;
            #pragma unroll
            for (int j = 0; j < 4; j++)
                Ps[(tk + j) * PQ + tq + i] = s[i][j];
        }
        __syncthreads();

        #pragma unroll
        for (int k = 0; k < 64; k++) {
            float4 a0 = *(const float4*)&Ps[k * PQ + tq];
            float4 a1 = *(const float4*)&Ps[k * PQ + tq + 4];
            float4 v4 = *(const float4*)&Vs[k * PK + tk];
            float ar[8] = {a0.x, a0.y, a0.z, a0.w, a1.x, a1.y, a1.z, a1.w};
            float vr[4] = {v4.x, v4.y, v4.z, v4.w};
            #pragma unroll
            for (int i = 0; i < 8; i++)
                #pragma unroll
                for (int j = 0; j < 4; j++)
                    o[i][j] += ar[i] * vr[j];
        }
        __syncthreads();
    }

    #pragma unroll
    for (int i = 0; i < 8; i++) {
        float inv = 1.f / (l[i] * 32.0f);
        float4 r;
        r.x = o[i][0] * inv; r.y = o[i][1] * inv;
        r.z = o[i][2] * inv; r.w = o[i][3] * inv;
        size_t off = ((size_t)(b * N_ + q0 + tq + i)) * D_ + h * HD_ + tk;
        *(float4*)&outp[off] = r;
    }
}

// ===================================================================
extern "C" void kernel_launch(void* const* d_in, const int* in_sizes, int n_in,
                              void* d_out, int out_size)
{
    const float* hidden = (const float*)d_in[0];
    const float* w      = (const float*)d_in[1];
    const float* ln_g   = (const float*)d_in[2];
    const float* ln_b   = (const float*)d_in[3];
    const float* Wg     = (const float*)d_in[4];
    const float* bg     = (const float*)d_in[5];
    const float* Wb     = (const float*)d_in[6];
    const float* bb     = (const float*)d_in[7];
    const float* Wqkv   = (const float*)d_in[8];
    const float* bqkv   = (const float*)d_in[9];
    const float* Wp     = (const float*)d_in[10];
    const float* bp     = (const float*)d_in[11];
    float* out = (float*)d_out;

    float *p_h, *p_qkv, *p_attn, *p_h1;
    __nv_bfloat16 *p_ahi, *p_alo, *p_bhi, *p_blo;
    cudaGetSymbolAddress((void**)&p_h, g_h);
    cudaGetSymbolAddress((void**)&p_qkv, g_qkv);
    cudaGetSymbolAddress((void**)&p_attn, g_attn);
    cudaGetSymbolAddress((void**)&p_h1, g_h1);
    cudaGetSymbolAddress((void**)&p_ahi, g_Ahi);
    cudaGetSymbolAddress((void**)&p_alo, g_Alo);
    cudaGetSymbolAddress((void**)&p_bhi, g_Bhi);
    cudaGetSymbolAddress((void**)&p_blo, g_Blo);

    cudaFuncSetAttribute(flash_kernel,
                         cudaFuncAttributeMaxDynamicSharedMemorySize, FLASH_SMEM);
    cudaFuncSetAttribute(gemm_mma,
                         cudaFuncAttributeMaxDynamicSharedMemorySize, GEMM_SMEM);

    // 1) gamma/beta
    gamma_beta_kernel<<<32, 256>>>(w, Wg, bg, Wb, bb);

    // 2) h = sln(hidden)
    sln_kernel<<<M_, 256>>>(hidden, ln_g, ln_b, p_h, 0);

    // 3) qkv = h @ Wqkv^T + bqkv  (mma.sync split-bf16)
    cvt_split<<<(M_ * D_) / 2048, 256>>>(p_h, p_ahi, p_alo);
    cvt_split<<<(QKV_ * D_) / 2048, 256>>>(Wqkv, p_bhi, p_blo);
    gemm_mma<<<dim3(QKV_ / 128, M_ / 128), 256, GEMM_SMEM>>>(
        p_ahi, p_alo, p_bhi, p_blo, bqkv, nullptr, p_qkv, M_, QKV_, D_);

    // 4) attention
    flash_kernel<<<dim3(N_ / 128, B_ * H_), 256, FLASH_SMEM>>>(p_attn);

    // 5) h1 = attn @ Wp^T + bp + hidden
    cvt_split<<<(M_ * D_) / 2048, 256>>>(p_attn, p_ahi, p_alo);
    cvt_split<<<(D_ * D_) / 2048, 256>>>(Wp, p_bhi, p_blo);
    gemm_mma<<<dim3(D_ / 128, M_ / 128), 256, GEMM_SMEM>>>(
        p_ahi, p_alo, p_bhi, p_blo, bp, hidden, p_h1, M_, D_, D_);

    // 6) out = sln(h1) + h1
    sln_kernel<<<M_, 256>>>(p_h1, ln_g, ln_b, out, 1);
}

// round 5
// speedup vs baseline: 2.0436x; 1.4338x over previous
#include <cuda_runtime.h>
#include <cuda_bf16.h>
#include <math.h>
#include <stdint.h>

// Shapes (fixed for this problem)
#define B_ 4
#define N_ 1024
#define D_ 1024
#define H_ 16
#define HD_ 64
#define M_ (B_ * N_)          // 4096 rows
#define QKV_ (3 * D_)         // 3072

// -------- scratch (no allocations allowed; __device__ globals) --------
__device__ float g_qkv[M_ * QKV_];    // qkv projections (fp32)
__device__ float g_h1[M_ * D_];       // residual stream after attn proj
__device__ float g_gamma[B_ * D_];
__device__ float g_beta[B_ * D_];
// bf16 split buffers (A = activations, B = weights)
__device__ __nv_bfloat16 g_Ahi[M_ * D_];
__device__ __nv_bfloat16 g_Alo[M_ * D_];
__device__ __nv_bfloat16 g_Bhi[QKV_ * D_];
__device__ __nv_bfloat16 g_Blo[QKV_ * D_];

__device__ __forceinline__ uint32_t smem_to_u32(const void* p) {
    uint32_t a;
    asm("{ .reg .u64 t; cvta.to.shared.u64 t, %1; cvt.u32.u64 %0, t; }"
        : "=r"(a) : "l"(p));
    return a;
}

// ===================================================================
// gamma/beta
// ===================================================================
__global__ __launch_bounds__(256) void gamma_beta_kernel(
    const float* __restrict__ w,
    const float* __restrict__ Wg, const float* __restrict__ bg,
    const float* __restrict__ Wb, const float* __restrict__ bb)
{
    int idx = blockIdx.x * 256 + threadIdx.x;
    int which = idx >> 12;
    int b = (idx >> 10) & 3;
    int d = idx & 1023;
    const float* Wrow = (which ? Wb : Wg) + (size_t)d * D_;
    const float* wr = w + b * D_;
    float acc = 0.f;
    #pragma unroll 4
    for (int k = 0; k < D_; k += 4) {
        float4 a = *(const float4*)&wr[k];
        float4 c = *(const float4*)&Wrow[k];
        acc += a.x * c.x + a.y * c.y + a.z * c.z + a.w * c.w;
    }
    if (which) g_beta[b * D_ + d]  = acc + bb[d];
    else       g_gamma[b * D_ + d] = acc + bg[d];
}

// ===================================================================
// split helper
// ===================================================================
__device__ __forceinline__ uint32_t split_pair(float f0, float f1, uint32_t& lo) {
    __nv_bfloat16 h0 = __float2bfloat16_rn(f0);
    __nv_bfloat16 h1 = __float2bfloat16_rn(f1);
    __nv_bfloat16 l0 = __float2bfloat16_rn(f0 - __bfloat162float(h0));
    __nv_bfloat16 l1 = __float2bfloat16_rn(f1 - __bfloat162float(h1));
    lo = (uint32_t)__bfloat16_as_ushort(l0) | ((uint32_t)__bfloat16_as_ushort(l1) << 16);
    return (uint32_t)__bfloat16_as_ushort(h0) | ((uint32_t)__bfloat16_as_ushort(h1) << 16);
}

// ===================================================================
// SLN. outf==null: write bf16 hi/lo split (feeds GEMM). else fp32 (+res).
// ===================================================================
__global__ __launch_bounds__(256) void sln_kernel(
    const float* __restrict__ x,
    const float* __restrict__ ln_g, const float* __restrict__ ln_b,
    float* __restrict__ outf,
    __nv_bfloat16* __restrict__ ohi, __nv_bfloat16* __restrict__ olo,
    int add_res)
{
    int row = blockIdx.x;
    int b = row >> 10;
    const float* xr = x + (size_t)row * D_;
    int t = threadIdx.x;

    float4 v = ((const float4*)xr)[t];
    float s  = v.x + v.y + v.z + v.w;
    float sq = v.x * v.x + v.y * v.y + v.z * v.z + v.w * v.w;
    #pragma unroll
    for (int o = 16; o; o >>= 1) {
        s  += __shfl_xor_sync(0xffffffffu, s, o);
        sq += __shfl_xor_sync(0xffffffffu, sq, o);
    }
    __shared__ float ss[8], ssq[8];
    int w = t >> 5, ln = t & 31;
    if (ln == 0) { ss[w] = s; ssq[w] = sq; }
    __syncthreads();
    s = 0.f; sq = 0.f;
    #pragma unroll
    for (int i = 0; i < 8; i++) { s += ss[i]; sq += ssq[i]; }

    float mu = s * (1.f / D_);
    float var = sq * (1.f / D_) - mu * mu;
    float rstd = rsqrtf(var + 1e-5f);

    float4 lg = ((const float4*)ln_g)[t];
    float4 lb = ((const float4*)ln_b)[t];
    float4 ga = ((const float4*)(g_gamma + b * D_))[t];
    float4 be = ((const float4*)(g_beta  + b * D_))[t];

    float4 r;
    r.x = ga.x * ((v.x - mu) * rstd * lg.x + lb.x) + be.x;
    r.y = ga.y * ((v.y - mu) * rstd * lg.y + lb.y) + be.y;
    r.z = ga.z * ((v.z - mu) * rstd * lg.z + lb.z) + be.z;
    r.w = ga.w * ((v.w - mu) * rstd * lg.w + lb.w) + be.w;
    if (add_res) { r.x += v.x; r.y += v.y; r.z += v.z; r.w += v.w; }
    if (outf) {
        ((float4*)(outf + (size_t)row * D_))[t] = r;
    } else {
        uint2 vh, vl;
        vh.x = split_pair(r.x, r.y, vl.x);
        vh.y = split_pair(r.z, r.w, vl.y);
        *(uint2*)(ohi + (size_t)row * D_ + t * 4) = vh;
        *(uint2*)(olo + (size_t)row * D_ + t * 4) = vl;
    }
}

// ===================================================================
// cvt_split (weights)
// ===================================================================
__global__ __launch_bounds__(256) void cvt_split(
    const float* __restrict__ src,
    __nv_bfloat16* __restrict__ hi, __nv_bfloat16* __restrict__ lo)
{
    int i = (blockIdx.x * 256 + threadIdx.x) * 8;
    float4 a = *(const float4*)(src + i);
    float4 b = *(const float4*)(src + i + 4);
    uint4 vh, vl;
    vh.x = split_pair(a.x, a.y, vl.x);
    vh.y = split_pair(a.z, a.w, vl.y);
    vh.z = split_pair(b.x, b.y, vl.z);
    vh.w = split_pair(b.z, b.w, vl.w);
    *(uint4*)(hi + i) = vh;
    *(uint4*)(lo + i) = vl;
}

// ===================================================================
// mma helpers
// ===================================================================
__device__ __forceinline__ void ldmx4(uint32_t* r, uint32_t addr) {
    asm volatile("ldmatrix.sync.aligned.m8n8.x4.shared.b16 {%0,%1,%2,%3}, [%4];"
                 : "=r"(r[0]), "=r"(r[1]), "=r"(r[2]), "=r"(r[3]) : "r"(addr));
}
__device__ __forceinline__ void ldmx2(uint32_t* r, uint32_t addr) {
    asm volatile("ldmatrix.sync.aligned.m8n8.x2.shared.b16 {%0,%1}, [%2];"
                 : "=r"(r[0]), "=r"(r[1]) : "r"(addr));
}
__device__ __forceinline__ void ldmx2t(uint32_t* r, uint32_t addr) {
    asm volatile("ldmatrix.sync.aligned.m8n8.x2.trans.shared.b16 {%0,%1}, [%2];"
                 : "=r"(r[0]), "=r"(r[1]) : "r"(addr));
}
__device__ __forceinline__ void mma16816(float* c, const uint32_t* a, const uint32_t* b) {
    asm volatile("mma.sync.aligned.m16n8k16.row.col.f32.bf16.bf16.f32 "
                 "{%0,%1,%2,%3}, {%4,%5,%6,%7}, {%8,%9}, {%0,%1,%2,%3};"
                 : "+f"(c[0]), "+f"(c[1]), "+f"(c[2]), "+f"(c[3])
                 : "r"(a[0]), "r"(a[1]), "r"(a[2]), "r"(a[3]), "r"(b[0]), "r"(b[1]));
}

// ===================================================================
// mma.sync bf16 GEMM (round-3 proven): C = A @ W^T + bias (+residual)
// ===================================================================
#define RS 40
#define MAT_ELEMS (128 * RS)
#define STAGE_ELEMS (4 * MAT_ELEMS)
#define GEMM_SMEM (2 * STAGE_ELEMS * 2)

__global__ __launch_bounds__(256) void gemm_mma(
    const __nv_bfloat16* __restrict__ Ahi, const __nv_bfloat16* __restrict__ Alo,
    const __nv_bfloat16* __restrict__ Bhi, const __nv_bfloat16* __restrict__ Blo,
    const float* __restrict__ bias, const float* __restrict__ residual,
    float* __restrict__ C, int M, int N, int K)
{
    extern __shared__ __nv_bfloat16 smb[];
    uint32_t sbase = smem_to_u32(smb);
    int tid = threadIdx.x, wid = tid >> 5, lane = tid & 31;
    int m0 = blockIdx.y * 128, n0 = blockIdx.x * 128;
    int wm = wid >> 2, wn = wid & 3;

    float acc[4][4][4];
    #pragma unroll
    for (int i = 0; i < 4; i++)
        #pragma unroll
        for (int j = 0; j < 4; j++)
            #pragma unroll
            for (int c = 0; c < 4; c++) acc[i][j][c] = 0.f;

    const int nch = K >> 5;

    auto load_stage = [&](int ch, int s) {
        int kk = ch << 5;
        #pragma unroll
        for (int t = 0; t < 8; t++) {
            int idx = t * 256 + tid;
            int mat = idx >> 9;
            int row = (idx >> 2) & 127;
            int seg = idx & 3;
            const __nv_bfloat16* src = (mat == 0) ? Ahi : (mat == 1) ? Alo
                                     : (mat == 2) ? Bhi : Blo;
            int rb = (mat < 2) ? m0 : n0;
            const __nv_bfloat16* g = src + (size_t)(rb + row) * K + kk + seg * 8;
            uint32_t dst = sbase + (uint32_t)((s * STAGE_ELEMS + mat * MAT_ELEMS
                                               + row * RS + seg * 8) * 2);
            asm volatile("cp.async.cg.shared.global [%0], [%1], 16;"
                         :: "r"(dst), "l"(g) : "memory");
        }
        asm volatile("cp.async.commit_group;" ::: "memory");
    };

    auto compute_stage = [&](int s) {
        uint32_t stage_b = sbase + (uint32_t)(s * STAGE_ELEMS * 2);
        #pragma unroll
        for (int ks = 0; ks < 2; ks++) {
            uint32_t ahi[4][4], alo[4][4];
            int arow = wm * 64 + (lane & 15);
            int acol = ks * 16 + (lane >> 4) * 8;
            #pragma unroll
            for (int i = 0; i < 4; i++) {
                uint32_t off = (uint32_t)(((arow + i * 16) * RS + acol) * 2);
                ldmx4(ahi[i], stage_b + 0 * MAT_ELEMS * 2 + off);
                ldmx4(alo[i], stage_b + 1 * MAT_ELEMS * 2 + off);
            }
            uint32_t bhi[4][2], blo[4][2];
            int bl = lane & 15;
            int brow = wn * 32 + (bl & 7);
            int bcol = ks * 16 + (bl >> 3) * 8;
            #pragma unroll
            for (int j = 0; j < 4; j++) {
                uint32_t off = (uint32_t)(((brow + j * 8) * RS + bcol) * 2);
                ldmx2(bhi[j], stage_b + 2 * MAT_ELEMS * 2 + off);
                ldmx2(blo[j], stage_b + 3 * MAT_ELEMS * 2 + off);
            }
            #pragma unroll
            for (int i = 0; i < 4; i++)
                #pragma unroll
                for (int j = 0; j < 4; j++) {
                    mma16816(acc[i][j], ahi[i], bhi[j]);
                    mma16816(acc[i][j], ahi[i], blo[j]);
                    mma16816(acc[i][j], alo[i], bhi[j]);
                }
        }
    };

    load_stage(0, 0);
    for (int ch = 0; ch < nch; ch++) {
        if (ch + 1 < nch) {
            load_stage(ch + 1, (ch + 1) & 1);
            asm volatile("cp.async.wait_group 1;" ::: "memory");
        } else {
            asm volatile("cp.async.wait_group 0;" ::: "memory");
        }
        __syncthreads();
        compute_stage(ch & 1);
        __syncthreads();
    }

    int r = lane >> 2, cp2 = (lane & 3) * 2;
    #pragma unroll
    for (int i = 0; i < 4; i++) {
        int row0 = m0 + wm * 64 + i * 16 + r;
        #pragma unroll
        for (int j = 0; j < 4; j++) {
            int col = n0 + wn * 32 + j * 8 + cp2;
            float2 bv = *(const float2*)(bias + col);
            float2 o0, o1;
            o0.x = acc[i][j][0] + bv.x; o0.y = acc[i][j][1] + bv.y;
            o1.x = acc[i][j][2] + bv.x; o1.y = acc[i][j][3] + bv.y;
            if (residual) {
                float2 r0 = *(const float2*)(residual + (size_t)row0 * N + col);
                float2 r1 = *(const float2*)(residual + (size_t)(row0 + 8) * N + col);
                o0.x += r0.x; o0.y += r0.y;
                o1.x += r1.x; o1.y += r1.y;
            }
            *(float2*)(C + (size_t)row0 * N + col) = o0;
            *(float2*)(C + (size_t)(row0 + 8) * N + col) = o1;
        }
    }
}

// ===================================================================
// Tensor-core flash attention. Q tile 128, key block 64, hd=64.
// 8 warps x 16 q-rows. Split-bf16 3-term for QK^T and PV.
// Output written directly as bf16 hi/lo split (feeds proj GEMM).
// ===================================================================
#define RS2 72                      // smem row stride in bf16 (64 + 8)
#define F_QHI 0
#define F_QLO (128 * RS2)
#define F_KHI (2 * 128 * RS2)
#define F_KLO (F_KHI + 64 * RS2)
#define F_VHI (F_KLO + 64 * RS2)
#define F_VLO (F_VHI + 64 * RS2)
#define FLASH_SMEM ((F_VLO + 64 * RS2) * 2)   // 73728 B

__global__ __launch_bounds__(256) void flash_tc(
    __nv_bfloat16* __restrict__ ohi, __nv_bfloat16* __restrict__ olo)
{
    extern __shared__ __nv_bfloat16 smb[];
    uint32_t sbase = smem_to_u32(smb);
    int tid = threadIdx.x, wid = tid >> 5, lane = tid & 31;
    int bh = blockIdx.y;
    int b = bh >> 4, h = bh & 15;
    int q0 = blockIdx.x * 128;
    size_t bas = (size_t)b * N_ * QKV_ + (size_t)h * 192;
    const float* qkv = g_qkv;

    // load Q tile (128 x 64), split into hi/lo
    #pragma unroll
    for (int it = 0; it < 32; it++) {
        int i = it * 256 + tid;
        int q = i >> 6, d = i & 63;
        float v = qkv[bas + (size_t)(q0 + q) * QKV_ + d * 3];
        __nv_bfloat16 hv = __float2bfloat16_rn(v);
        smb[F_QHI + q * RS2 + d] = hv;
        smb[F_QLO + q * RS2 + d] = __float2bfloat16_rn(v - __bfloat162float(hv));
    }

    float mr0 = -1e30f, mr1 = -1e30f, l0 = 0.f, l1 = 0.f;
    float O[8][4] = {};

    for (int kb = 0; kb < N_; kb += 64) {
        __syncthreads();   // prev-iter smem reads done (covers Q writes on iter 0)
        #pragma unroll
        for (int it = 0; it < 16; it++) {
            int i = it * 256 + tid;
            int r = i >> 6, d = i & 63;
            size_t p = bas + (size_t)(kb + r) * QKV_ + d * 3;
            float kv = qkv[p + 1];
            __nv_bfloat16 kh = __float2bfloat16_rn(kv);
            smb[F_KHI + r * RS2 + d] = kh;
            smb[F_KLO + r * RS2 + d] = __float2bfloat16_rn(kv - __bfloat162float(kh));
            float vv = qkv[p + 2];
            __nv_bfloat16 vh = __float2bfloat16_rn(vv);
            smb[F_VHI + r * RS2 + d] = vh;
            smb[F_VLO + r * RS2 + d] = __float2bfloat16_rn(vv - __bfloat162float(vh));
        }
        __syncthreads();

        // ---- S = Q K^T (16 x 64 per warp) ----
        float S[8][4];
        #pragma unroll
        for (int j = 0; j < 8; j++)
            #pragma unroll
            for (int c = 0; c < 4; c++) S[j][c] = 0.f;

        #pragma unroll
        for (int ks = 0; ks < 4; ks++) {
            uint32_t qh[4], ql[4];
            uint32_t aoff = (uint32_t)(((wid * 16 + (lane & 15)) * RS2
                                        + ks * 16 + (lane >> 4) * 8) * 2);
            ldmx4(qh, sbase + F_QHI * 2 + aoff);
            ldmx4(ql, sbase + F_QLO * 2 + aoff);
            #pragma unroll
            for (int j = 0; j < 8; j++) {
                uint32_t kh[2], kl[2];
                uint32_t boff = (uint32_t)(((j * 8 + (lane & 7)) * RS2
                                            + ks * 16 + ((lane & 15) >> 3) * 8) * 2);
                ldmx2(kh, sbase + F_KHI * 2 + boff);
                ldmx2(kl, sbase + F_KLO * 2 + boff);
                mma16816(S[j], qh, kh);
                mma16816(S[j], qh, kl);
                mma16816(S[j], ql, kh);
            }
        }

        // ---- online softmax (rows r = lane>>2 and r+8) ----
        float rm0 = -1e30f, rm1 = -1e30f;
        #pragma unroll
        for (int j = 0; j < 8; j++) {
            rm0 = fmaxf(rm0, fmaxf(S[j][0], S[j][1]));
            rm1 = fmaxf(rm1, fmaxf(S[j][2], S[j][3]));
        }
        rm0 = fmaxf(rm0, __shfl_xor_sync(0xffffffffu, rm0, 1));
        rm0 = fmaxf(rm0, __shfl_xor_sync(0xffffffffu, rm0, 2));
        rm1 = fmaxf(rm1, __shfl_xor_sync(0xffffffffu, rm1, 1));
        rm1 = fmaxf(rm1, __shfl_xor_sync(0xffffffffu, rm1, 2));
        float mn0 = fmaxf(mr0, rm0), mn1 = fmaxf(mr1, rm1);
        float sc0 = __expf(mr0 - mn0), sc1 = __expf(mr1 - mn1);
        float rs0 = 0.f, rs1 = 0.f;
        #pragma unroll
        for (int j = 0; j < 8; j++) {
            S[j][0] = __expf(S[j][0] - mn0);
            S[j][1] = __expf(S[j][1] - mn0);
            S[j][2] = __expf(S[j][2] - mn1);
            S[j][3] = __expf(S[j][3] - mn1);
            rs0 += S[j][0] + S[j][1];
            rs1 += S[j][2] + S[j][3];
        }
        rs0 += __shfl_xor_sync(0xffffffffu, rs0, 1);
        rs0 += __shfl_xor_sync(0xffffffffu, rs0, 2);
        rs1 += __shfl_xor_sync(0xffffffffu, rs1, 1);
        rs1 += __shfl_xor_sync(0xffffffffu, rs1, 2);
        l0 = l0 * sc0 + rs0;
        l1 = l1 * sc1 + rs1;
        mr0 = mn0; mr1 = mn1;
        #pragma unroll
        for (int j = 0; j < 8; j++) {
            O[j][0] *= sc0; O[j][1] *= sc0;
            O[j][2] *= sc1; O[j][3] *= sc1;
        }

        // ---- O += P V : P frags from S accum (FA2 register repack) ----
        #pragma unroll
        for (int t = 0; t < 4; t++) {
            uint32_t ph[4], pl[4];
            ph[0] = split_pair(S[2 * t][0],     S[2 * t][1],     pl[0]);
            ph[1] = split_pair(S[2 * t][2],     S[2 * t][3],     pl[1]);
            ph[2] = split_pair(S[2 * t + 1][0], S[2 * t + 1][1], pl[2]);
            ph[3] = split_pair(S[2 * t + 1][2], S[2 * t + 1][3], pl[3]);
            #pragma unroll
            for (int dt = 0; dt < 8; dt++) {
                uint32_t vh[2], vl[2];
                uint32_t voff = (uint32_t)(((t * 16 + (lane & 15)) * RS2 + dt * 8) * 2);
                ldmx2t(vh, sbase + F_VHI * 2 + voff);
                ldmx2t(vl, sbase + F_VLO * 2 + voff);
                mma16816(O[dt], ph, vh);
                mma16816(O[dt], ph, vl);
                mma16816(O[dt], pl, vh);
            }
        }
    }

    // ---- epilogue: normalize (softmax denom + /32 quirk), split-store ----
    float inv0 = 1.f / (l0 * 32.f), inv1 = 1.f / (l1 * 32.f);
    int r = lane >> 2, c2 = (lane & 3) * 2;
    int q = q0 + wid * 16 + r;
    #pragma unroll
    for (int dt = 0; dt < 8; dt++) {
        int col = h * 64 + dt * 8 + c2;
        uint32_t lo0, lo1;
        uint32_t hi0 = split_pair(O[dt][0] * inv0, O[dt][1] * inv0, lo0);
        uint32_t hi1 = split_pair(O[dt][2] * inv1, O[dt][3] * inv1, lo1);
        size_t off0 = (size_t)(b * N_ + q) * D_ + col;
        size_t off1 = (size_t)(b * N_ + q + 8) * D_ + col;
        *(uint32_t*)(ohi + off0) = hi0;
        *(uint32_t*)(olo + off0) = lo0;
        *(uint32_t*)(ohi + off1) = hi1;
        *(uint32_t*)(olo + off1) = lo1;
    }
}

// ===================================================================
extern "C" void kernel_launch(void* const* d_in, const int* in_sizes, int n_in,
                              void* d_out, int out_size)
{
    const float* hidden = (const float*)d_in[0];
    const float* w      = (const float*)d_in[1];
    const float* ln_g   = (const float*)d_in[2];
    const float* ln_b   = (const float*)d_in[3];
    const float* Wg     = (const float*)d_in[4];
    const float* bg     = (const float*)d_in[5];
    const float* Wb     = (const float*)d_in[6];
    const float* bb     = (const float*)d_in[7];
    const float* Wqkv   = (const float*)d_in[8];
    const float* bqkv   = (const float*)d_in[9];
    const float* Wp     = (const float*)d_in[10];
    const float* bp     = (const float*)d_in[11];
    float* out = (float*)d_out;

    float *p_qkv, *p_h1;
    __nv_bfloat16 *p_ahi, *p_alo, *p_bhi, *p_blo;
    cudaGetSymbolAddress((void**)&p_qkv, g_qkv);
    cudaGetSymbolAddress((void**)&p_h1, g_h1);
    cudaGetSymbolAddress((void**)&p_ahi, g_Ahi);
    cudaGetSymbolAddress((void**)&p_alo, g_Alo);
    cudaGetSymbolAddress((void**)&p_bhi, g_Bhi);
    cudaGetSymbolAddress((void**)&p_blo, g_Blo);

    cudaFuncSetAttribute(flash_tc,
                         cudaFuncAttributeMaxDynamicSharedMemorySize, FLASH_SMEM);
    cudaFuncSetAttribute(gemm_mma,
                         cudaFuncAttributeMaxDynamicSharedMemorySize, GEMM_SMEM);

    // 1) gamma/beta
    gamma_beta_kernel<<<32, 256>>>(w, Wg, bg, Wb, bb);

    // 2) h = sln(hidden) -> bf16 hi/lo directly
    sln_kernel<<<M_, 256>>>(hidden, ln_g, ln_b, nullptr, p_ahi, p_alo, 0);

    // 3) qkv = h @ Wqkv^T + bqkv
    cvt_split<<<(QKV_ * D_) / 2048, 256>>>(Wqkv, p_bhi, p_blo);
    gemm_mma<<<dim3(QKV_ / 128, M_ / 128), 256, GEMM_SMEM>>>(
        p_ahi, p_alo, p_bhi, p_blo, bqkv, nullptr, p_qkv, M_, QKV_, D_);

    // 4) attention (tensor-core), writes bf16 hi/lo attn output
    flash_tc<<<dim3(N_ / 128, B_ * H_), 256, FLASH_SMEM>>>(p_ahi, p_alo);

    // 5) h1 = attn @ Wp^T + bp + hidden
    cvt_split<<<(D_ * D_) / 2048, 256>>>(Wp, p_bhi, p_blo);
    gemm_mma<<<dim3(D_ / 128, M_ / 128), 256, GEMM_SMEM>>>(
        p_ahi, p_alo, p_bhi, p_blo, bp, hidden, p_h1, M_, D_, D_);

    // 6) out = sln(h1) + h1
    sln_kernel<<<M_, 256>>>(p_h1, ln_g, ln_b, out, nullptr, nullptr, 1);
}

// round 6
// speedup vs baseline: 2.1952x; 1.0742x over previous
#include <cuda_runtime.h>
#include <cuda_bf16.h>
#include <math.h>
#include <stdint.h>

// Shapes (fixed for this problem)
#define B_ 4
#define N_ 1024
#define D_ 1024
#define H_ 16
#define HD_ 64
#define M_ (B_ * N_)          // 4096 rows
#define QKV_ (3 * D_)         // 3072

// -------- scratch (no allocations allowed; __device__ globals) --------
__device__ float g_qkv[M_ * QKV_];    // qkv projections, layout [b,n][which*1024+h*64+d]
__device__ float g_h1[M_ * D_];
__device__ float g_gamma[B_ * D_];
__device__ float g_beta[B_ * D_];
__device__ float g_bqkv[QKV_];        // permuted qkv bias
// bf16 split buffers
__device__ __nv_bfloat16 g_Ahi[M_ * D_];
__device__ __nv_bfloat16 g_Alo[M_ * D_];
__device__ __nv_bfloat16 g_Bhi[QKV_ * D_];
__device__ __nv_bfloat16 g_Blo[QKV_ * D_];

__device__ __forceinline__ uint32_t smem_to_u32(const void* p) {
    uint32_t a;
    asm("{ .reg .u64 t; cvta.to.shared.u64 t, %1; cvt.u32.u64 %0, t; }"
        : "=r"(a) : "l"(p));
    return a;
}

// ===================================================================
// gamma/beta
// ===================================================================
__global__ __launch_bounds__(256) void gamma_beta_kernel(
    const float* __restrict__ w,
    const float* __restrict__ Wg, const float* __restrict__ bg,
    const float* __restrict__ Wb, const float* __restrict__ bb)
{
    int idx = blockIdx.x * 256 + threadIdx.x;
    int which = idx >> 12;
    int b = (idx >> 10) & 3;
    int d = idx & 1023;
    const float* Wrow = (which ? Wb : Wg) + (size_t)d * D_;
    const float* wr = w + b * D_;
    float acc = 0.f;
    #pragma unroll 4
    for (int k = 0; k < D_; k += 4) {
        float4 a = *(const float4*)&wr[k];
        float4 c = *(const float4*)&Wrow[k];
        acc += a.x * c.x + a.y * c.y + a.z * c.z + a.w * c.w;
    }
    if (which) g_beta[b * D_ + d]  = acc + bb[d];
    else       g_gamma[b * D_ + d] = acc + bg[d];
}

// ===================================================================
// split helper
// ===================================================================
__device__ __forceinline__ uint32_t split_pair(float f0, float f1, uint32_t& lo) {
    __nv_bfloat16 h0 = __float2bfloat16_rn(f0);
    __nv_bfloat16 h1 = __float2bfloat16_rn(f1);
    __nv_bfloat16 l0 = __float2bfloat16_rn(f0 - __bfloat162float(h0));
    __nv_bfloat16 l1 = __float2bfloat16_rn(f1 - __bfloat162float(h1));
    lo = (uint32_t)__bfloat16_as_ushort(l0) | ((uint32_t)__bfloat16_as_ushort(l1) << 16);
    return (uint32_t)__bfloat16_as_ushort(h0) | ((uint32_t)__bfloat16_as_ushort(h1) << 16);
}

// ===================================================================
// SLN. outf==null: write bf16 hi/lo split. else fp32 (+res).
// ===================================================================
__global__ __launch_bounds__(256) void sln_kernel(
    const float* __restrict__ x,
    const float* __restrict__ ln_g, const float* __restrict__ ln_b,
    float* __restrict__ outf,
    __nv_bfloat16* __restrict__ ohi, __nv_bfloat16* __restrict__ olo,
    int add_res)
{
    int row = blockIdx.x;
    int b = row >> 10;
    const float* xr = x + (size_t)row * D_;
    int t = threadIdx.x;

    float4 v = ((const float4*)xr)[t];
    float s  = v.x + v.y + v.z + v.w;
    float sq = v.x * v.x + v.y * v.y + v.z * v.z + v.w * v.w;
    #pragma unroll
    for (int o = 16; o; o >>= 1) {
        s  += __shfl_xor_sync(0xffffffffu, s, o);
        sq += __shfl_xor_sync(0xffffffffu, sq, o);
    }
    __shared__ float ss[8], ssq[8];
    int w = t >> 5, ln = t & 31;
    if (ln == 0) { ss[w] = s; ssq[w] = sq; }
    __syncthreads();
    s = 0.f; sq = 0.f;
    #pragma unroll
    for (int i = 0; i < 8; i++) { s += ss[i]; sq += ssq[i]; }

    float mu = s * (1.f / D_);
    float var = sq * (1.f / D_) - mu * mu;
    float rstd = rsqrtf(var + 1e-5f);

    float4 lg = ((const float4*)ln_g)[t];
    float4 lb = ((const float4*)ln_b)[t];
    float4 ga = ((const float4*)(g_gamma + b * D_))[t];
    float4 be = ((const float4*)(g_beta  + b * D_))[t];

    float4 r;
    r.x = ga.x * ((v.x - mu) * rstd * lg.x + lb.x) + be.x;
    r.y = ga.y * ((v.y - mu) * rstd * lg.y + lb.y) + be.y;
    r.z = ga.z * ((v.z - mu) * rstd * lg.z + lb.z) + be.z;
    r.w = ga.w * ((v.w - mu) * rstd * lg.w + lb.w) + be.w;
    if (add_res) { r.x += v.x; r.y += v.y; r.z += v.z; r.w += v.w; }
    if (outf) {
        ((float4*)(outf + (size_t)row * D_))[t] = r;
    } else {
        uint2 vh, vl;
        vh.x = split_pair(r.x, r.y, vl.x);
        vh.y = split_pair(r.z, r.w, vl.y);
        *(uint2*)(ohi + (size_t)row * D_ + t * 4) = vh;
        *(uint2*)(olo + (size_t)row * D_ + t * 4) = vl;
    }
}

// ===================================================================
// cvt_split (plain, for Wp)
// ===================================================================
__global__ __launch_bounds__(256) void cvt_split(
    const float* __restrict__ src,
    __nv_bfloat16* __restrict__ hi, __nv_bfloat16* __restrict__ lo)
{
    int i = (blockIdx.x * 256 + threadIdx.x) * 8;
    float4 a = *(const float4*)(src + i);
    float4 b = *(const float4*)(src + i + 4);
    uint4 vh, vl;
    vh.x = split_pair(a.x, a.y, vl.x);
    vh.y = split_pair(a.z, a.w, vl.y);
    vh.z = split_pair(b.x, b.y, vl.z);
    vh.w = split_pair(b.z, b.w, vl.w);
    *(uint4*)(hi + i) = vh;
    *(uint4*)(lo + i) = vl;
}

// ===================================================================
// cvt_split with qkv row permutation: src row r = h*192 + d*3 + which
// -> dst row which*1024 + h*64 + d. Also permutes nothing else.
// ===================================================================
__global__ __launch_bounds__(256) void cvt_split_permW(
    const float* __restrict__ src,
    __nv_bfloat16* __restrict__ hi, __nv_bfloat16* __restrict__ lo)
{
    int idx = (blockIdx.x * 256 + threadIdx.x) * 8;   // over 3072*1024
    int row = idx >> 10, col = idx & 1023;
    int h = row / 192, rem = row % 192;
    int d = rem / 3, wh = rem % 3;
    size_t dst = ((size_t)(wh * 1024 + h * 64 + d) << 10) + col;
    float4 a = *(const float4*)(src + idx);
    float4 b = *(const float4*)(src + idx + 4);
    uint4 vh, vl;
    vh.x = split_pair(a.x, a.y, vl.x);
    vh.y = split_pair(a.z, a.w, vl.y);
    vh.z = split_pair(b.x, b.y, vl.z);
    vh.w = split_pair(b.z, b.w, vl.w);
    *(uint4*)(hi + dst) = vh;
    *(uint4*)(lo + dst) = vl;
}

__global__ void permute_bias(const float* __restrict__ b) {
    int r = blockIdx.x * 256 + threadIdx.x;
    if (r < QKV_) {
        int h = r / 192, rem = r % 192;
        int d = rem / 3, wh = rem % 3;
        g_bqkv[wh * 1024 + h * 64 + d] = b[r];
    }
}

// ===================================================================
// mma helpers
// ===================================================================
__device__ __forceinline__ void ldmx4(uint32_t* r, uint32_t addr) {
    asm volatile("ldmatrix.sync.aligned.m8n8.x4.shared.b16 {%0,%1,%2,%3}, [%4];"
                 : "=r"(r[0]), "=r"(r[1]), "=r"(r[2]), "=r"(r[3]) : "r"(addr));
}
__device__ __forceinline__ void ldmx2(uint32_t* r, uint32_t addr) {
    asm volatile("ldmatrix.sync.aligned.m8n8.x2.shared.b16 {%0,%1}, [%2];"
                 : "=r"(r[0]), "=r"(r[1]) : "r"(addr));
}
__device__ __forceinline__ void ldmx2t(uint32_t* r, uint32_t addr) {
    asm volatile("ldmatrix.sync.aligned.m8n8.x2.trans.shared.b16 {%0,%1}, [%2];"
                 : "=r"(r[0]), "=r"(r[1]) : "r"(addr));
}
__device__ __forceinline__ void mma16816(float* c, const uint32_t* a, const uint32_t* b) {
    asm volatile("mma.sync.aligned.m16n8k16.row.col.f32.bf16.bf16.f32 "
                 "{%0,%1,%2,%3}, {%4,%5,%6,%7}, {%8,%9}, {%0,%1,%2,%3};"
                 : "+f"(c[0]), "+f"(c[1]), "+f"(c[2]), "+f"(c[3])
                 : "r"(a[0]), "r"(a[1]), "r"(a[2]), "r"(a[3]), "r"(b[0]), "r"(b[1]));
}

// ===================================================================
// mma.sync bf16 GEMM, BK=64, 2-stage cp.async pipeline.
// C[M,N] = A @ W^T + bias (+residual). CTA 128x128, 8 warps (2x4).
// ===================================================================
#define RSG 72                          // 64 + 8 pad, bf16 units
#define MAT_ELEMS (128 * RSG)           // 9216
#define STAGE_ELEMS (4 * MAT_ELEMS)     // 36864
#define GEMM_SMEM (2 * STAGE_ELEMS * 2) // 147456 B

__global__ __launch_bounds__(256) void gemm_mma(
    const __nv_bfloat16* __restrict__ Ahi, const __nv_bfloat16* __restrict__ Alo,
    const __nv_bfloat16* __restrict__ Bhi, const __nv_bfloat16* __restrict__ Blo,
    const float* __restrict__ bias, const float* __restrict__ residual,
    float* __restrict__ C, int M, int N, int K)
{
    extern __shared__ __nv_bfloat16 smb[];
    uint32_t sbase = smem_to_u32(smb);
    int tid = threadIdx.x, wid = tid >> 5, lane = tid & 31;
    int m0 = blockIdx.y * 128, n0 = blockIdx.x * 128;
    int wm = wid >> 2, wn = wid & 3;

    float acc[4][4][4];
    #pragma unroll
    for (int i = 0; i < 4; i++)
        #pragma unroll
        for (int j = 0; j < 4; j++)
            #pragma unroll
            for (int c = 0; c < 4; c++) acc[i][j][c] = 0.f;

    const int nch = K >> 6;   // BK=64

    auto load_stage = [&](int ch, int s) {
        int kk = ch << 6;
        #pragma unroll
        for (int t = 0; t < 16; t++) {
            int idx = t * 256 + tid;        // 0..4095
            int mat = idx >> 10;            // 0..3 (constant per t)
            int row = (idx >> 3) & 127;
            int seg = idx & 7;              // 8 cols each
            const __nv_bfloat16* src = (mat == 0) ? Ahi : (mat == 1) ? Alo
                                     : (mat == 2) ? Bhi : Blo;
            int rb = (mat < 2) ? m0 : n0;
            const __nv_bfloat16* g = src + (size_t)(rb + row) * K + kk + seg * 8;
            uint32_t dst = sbase + (uint32_t)((s * STAGE_ELEMS + mat * MAT_ELEMS
                                               + row * RSG + seg * 8) * 2);
            asm volatile("cp.async.cg.shared.global [%0], [%1], 16;"
                         :: "r"(dst), "l"(g) : "memory");
        }
        asm volatile("cp.async.commit_group;" ::: "memory");
    };

    auto compute_stage = [&](int s) {
        uint32_t stage_b = sbase + (uint32_t)(s * STAGE_ELEMS * 2);
        #pragma unroll
        for (int ks = 0; ks < 4; ks++) {
            uint32_t ahi[4][4], alo[4][4];
            int arow = wm * 64 + (lane & 15);
            int acol = ks * 16 + (lane >> 4) * 8;
            #pragma unroll
            for (int i = 0; i < 4; i++) {
                uint32_t off = (uint32_t)(((arow + i * 16) * RSG + acol) * 2);
                ldmx4(ahi[i], stage_b + 0 * MAT_ELEMS * 2 + off);
                ldmx4(alo[i], stage_b + 1 * MAT_ELEMS * 2 + off);
            }
            uint32_t bhi[4][2], blo[4][2];
            int bl = lane & 15;
            int brow = wn * 32 + (bl & 7);
            int bcol = ks * 16 + (bl >> 3) * 8;
            #pragma unroll
            for (int j = 0; j < 4; j++) {
                uint32_t off = (uint32_t)(((brow + j * 8) * RSG + bcol) * 2);
                ldmx2(bhi[j], stage_b + 2 * MAT_ELEMS * 2 + off);
                ldmx2(blo[j], stage_b + 3 * MAT_ELEMS * 2 + off);
            }
            #pragma unroll
            for (int i = 0; i < 4; i++)
                #pragma unroll
                for (int j = 0; j < 4; j++) {
                    mma16816(acc[i][j], ahi[i], bhi[j]);
                    mma16816(acc[i][j], ahi[i], blo[j]);
                    mma16816(acc[i][j], alo[i], bhi[j]);
                }
        }
    };

    load_stage(0, 0);
    for (int ch = 0; ch < nch; ch++) {
        if (ch + 1 < nch) {
            load_stage(ch + 1, (ch + 1) & 1);
            asm volatile("cp.async.wait_group 1;" ::: "memory");
        } else {
            asm volatile("cp.async.wait_group 0;" ::: "memory");
        }
        __syncthreads();
        compute_stage(ch & 1);
        __syncthreads();
    }

    int r = lane >> 2, cp2 = (lane & 3) * 2;
    #pragma unroll
    for (int i = 0; i < 4; i++) {
        int row0 = m0 + wm * 64 + i * 16 + r;
        #pragma unroll
        for (int j = 0; j < 4; j++) {
            int col = n0 + wn * 32 + j * 8 + cp2;
            float2 bv = *(const float2*)(bias + col);
            float2 o0, o1;
            o0.x = acc[i][j][0] + bv.x; o0.y = acc[i][j][1] + bv.y;
            o1.x = acc[i][j][2] + bv.x; o1.y = acc[i][j][3] + bv.y;
            if (residual) {
                float2 r0 = *(const float2*)(residual + (size_t)row0 * N + col);
                float2 r1 = *(const float2*)(residual + (size_t)(row0 + 8) * N + col);
                o0.x += r0.x; o0.y += r0.y;
                o1.x += r1.x; o1.y += r1.y;
            }
            *(float2*)(C + (size_t)row0 * N + col) = o0;
            *(float2*)(C + (size_t)(row0 + 8) * N + col) = o1;
        }
    }
}

// ===================================================================
// Tensor-core flash attention, qkv layout [b,n][which*1024 + h*64 + d]
// (coalesced float4 loads). Q tile 128, key block 64, hd=64. 8 warps.
// ===================================================================
#define RS2 72
#define F_QHI 0
#define F_QLO (128 * RS2)
#define F_KHI (2 * 128 * RS2)
#define F_KLO (F_KHI + 64 * RS2)
#define F_VHI (F_KLO + 64 * RS2)
#define F_VLO (F_VHI + 64 * RS2)
#define FLASH_SMEM ((F_VLO + 64 * RS2) * 2)   // 73728 B

__global__ __launch_bounds__(256) void flash_tc(
    __nv_bfloat16* __restrict__ ohi, __nv_bfloat16* __restrict__ olo)
{
    extern __shared__ __nv_bfloat16 smb[];
    uint32_t sbase = smem_to_u32(smb);
    int tid = threadIdx.x, wid = tid >> 5, lane = tid & 31;
    int bh = blockIdx.y;
    int b = bh >> 4, h = bh & 15;
    int q0 = blockIdx.x * 128;
    const float* qkv = g_qkv;
    size_t rowbase = (size_t)(b * N_) * QKV_ + h * 64;

    // Q tile 128x64, coalesced float4
    #pragma unroll
    for (int it = 0; it < 8; it++) {
        int i = it * 256 + tid;             // 0..2047
        int q = i >> 4, dg = (i & 15) * 4;
        float4 v = *(const float4*)(qkv + rowbase + (size_t)(q0 + q) * QKV_ + dg);
        uint32_t lo0, lo1;
        uint32_t hi0 = split_pair(v.x, v.y, lo0);
        uint32_t hi1 = split_pair(v.z, v.w, lo1);
        uint32_t o = q * RS2 + dg;
        *(uint32_t*)(smb + F_QHI + o) = hi0;
        *(uint32_t*)(smb + F_QHI + o + 2) = hi1;
        *(uint32_t*)(smb + F_QLO + o) = lo0;
        *(uint32_t*)(smb + F_QLO + o + 2) = lo1;
    }

    float mr0 = -1e30f, mr1 = -1e30f, l0 = 0.f, l1 = 0.f;
    float O[8][4] = {};

    for (int kb = 0; kb < N_; kb += 64) {
        __syncthreads();   // prev-iter reads done (covers Q writes on iter 0)
        #pragma unroll
        for (int it = 0; it < 4; it++) {
            int i = it * 256 + tid;         // 0..1023
            int r = i >> 4, dg = (i & 15) * 4;
            size_t p = rowbase + (size_t)(kb + r) * QKV_ + dg;
            float4 kv = *(const float4*)(qkv + p + 1024);
            float4 vv = *(const float4*)(qkv + p + 2048);
            uint32_t lo0, lo1;
            uint32_t hi0 = split_pair(kv.x, kv.y, lo0);
            uint32_t hi1 = split_pair(kv.z, kv.w, lo1);
            uint32_t o = r * RS2 + dg;
            *(uint32_t*)(smb + F_KHI + o) = hi0;
            *(uint32_t*)(smb + F_KHI + o + 2) = hi1;
            *(uint32_t*)(smb + F_KLO + o) = lo0;
            *(uint32_t*)(smb + F_KLO + o + 2) = lo1;
            hi0 = split_pair(vv.x, vv.y, lo0);
            hi1 = split_pair(vv.z, vv.w, lo1);
            *(uint32_t*)(smb + F_VHI + o) = hi0;
            *(uint32_t*)(smb + F_VHI + o + 2) = hi1;
            *(uint32_t*)(smb + F_VLO + o) = lo0;
            *(uint32_t*)(smb + F_VLO + o + 2) = lo1;
        }
        __syncthreads();

        // ---- S = Q K^T (16 x 64 per warp) ----
        float S[8][4];
        #pragma unroll
        for (int j = 0; j < 8; j++)
            #pragma unroll
            for (int c = 0; c < 4; c++) S[j][c] = 0.f;

        #pragma unroll
        for (int ks = 0; ks < 4; ks++) {
            uint32_t qh[4], ql[4];
            uint32_t aoff = (uint32_t)(((wid * 16 + (lane & 15)) * RS2
                                        + ks * 16 + (lane >> 4) * 8) * 2);
            ldmx4(qh, sbase + F_QHI * 2 + aoff);
            ldmx4(ql, sbase + F_QLO * 2 + aoff);
            #pragma unroll
            for (int j = 0; j < 8; j++) {
                uint32_t kh[2], kl[2];
                uint32_t boff = (uint32_t)(((j * 8 + (lane & 7)) * RS2
                                            + ks * 16 + ((lane & 15) >> 3) * 8) * 2);
                ldmx2(kh, sbase + F_KHI * 2 + boff);
                ldmx2(kl, sbase + F_KLO * 2 + boff);
                mma16816(S[j], qh, kh);
                mma16816(S[j], qh, kl);
                mma16816(S[j], ql, kh);
            }
        }

        // ---- online softmax (rows r = lane>>2 and r+8) ----
        float rm0 = -1e30f, rm1 = -1e30f;
        #pragma unroll
        for (int j = 0; j < 8; j++) {
            rm0 = fmaxf(rm0, fmaxf(S[j][0], S[j][1]));
            rm1 = fmaxf(rm1, fmaxf(S[j][2], S[j][3]));
        }
        rm0 = fmaxf(rm0, __shfl_xor_sync(0xffffffffu, rm0, 1));
        rm0 = fmaxf(rm0, __shfl_xor_sync(0xffffffffu, rm0, 2));
        rm1 = fmaxf(rm1, __shfl_xor_sync(0xffffffffu, rm1, 1));
        rm1 = fmaxf(rm1, __shfl_xor_sync(0xffffffffu, rm1, 2));
        float mn0 = fmaxf(mr0, rm0), mn1 = fmaxf(mr1, rm1);
        float sc0 = __expf(mr0 - mn0), sc1 = __expf(mr1 - mn1);
        float rs0 = 0.f, rs1 = 0.f;
        #pragma unroll
        for (int j = 0; j < 8; j++) {
            S[j][0] = __expf(S[j][0] - mn0);
            S[j][1] = __expf(S[j][1] - mn0);
            S[j][2] = __expf(S[j][2] - mn1);
            S[j][3] = __expf(S[j][3] - mn1);
            rs0 += S[j][0] + S[j][1];
            rs1 += S[j][2] + S[j][3];
        }
        rs0 += __shfl_xor_sync(0xffffffffu, rs0, 1);
        rs0 += __shfl_xor_sync(0xffffffffu, rs0, 2);
        rs1 += __shfl_xor_sync(0xffffffffu, rs1, 1);
        rs1 += __shfl_xor_sync(0xffffffffu, rs1, 2);
        l0 = l0 * sc0 + rs0;
        l1 = l1 * sc1 + rs1;
        mr0 = mn0; mr1 = mn1;
        #pragma unroll
        for (int j = 0; j < 8; j++) {
            O[j][0] *= sc0; O[j][1] *= sc0;
            O[j][2] *= sc1; O[j][3] *= sc1;
        }

        // ---- O += P V (FA2 register repack) ----
        #pragma unroll
        for (int t = 0; t < 4; t++) {
            uint32_t ph[4], pl[4];
            ph[0] = split_pair(S[2 * t][0],     S[2 * t][1],     pl[0]);
            ph[1] = split_pair(S[2 * t][2],     S[2 * t][3],     pl[1]);
            ph[2] = split_pair(S[2 * t + 1][0], S[2 * t + 1][1], pl[2]);
            ph[3] = split_pair(S[2 * t + 1][2], S[2 * t + 1][3], pl[3]);
            #pragma unroll
            for (int dt = 0; dt < 8; dt++) {
                uint32_t vh[2], vl[2];
                uint32_t voff = (uint32_t)(((t * 16 + (lane & 15)) * RS2 + dt * 8) * 2);
                ldmx2t(vh, sbase + F_VHI * 2 + voff);
                ldmx2t(vl, sbase + F_VLO * 2 + voff);
                mma16816(O[dt], ph, vh);
                mma16816(O[dt], ph, vl);
                mma16816(O[dt], pl, vh);
            }
        }
    }

    // ---- epilogue: normalize (softmax denom + /32 quirk), split-store ----
    float inv0 = 1.f / (l0 * 32.f), inv1 = 1.f / (l1 * 32.f);
    int r = lane >> 2, c2 = (lane & 3) * 2;
    int q = q0 + wid * 16 + r;
    #pragma unroll
    for (int dt = 0; dt < 8; dt++) {
        int col = h * 64 + dt * 8 + c2;
        uint32_t lo0, lo1;
        uint32_t hi0 = split_pair(O[dt][0] * inv0, O[dt][1] * inv0, lo0);
        uint32_t hi1 = split_pair(O[dt][2] * inv1, O[dt][3] * inv1, lo1);
        size_t off0 = (size_t)(b * N_ + q) * D_ + col;
        size_t off1 = (size_t)(b * N_ + q + 8) * D_ + col;
        *(uint32_t*)(ohi + off0) = hi0;
        *(uint32_t*)(olo + off0) = lo0;
        *(uint32_t*)(ohi + off1) = hi1;
        *(uint32_t*)(olo + off1) = lo1;
    }
}

// ===================================================================
extern "C" void kernel_launch(void* const* d_in, const int* in_sizes, int n_in,
                              void* d_out, int out_size)
{
    const float* hidden = (const float*)d_in[0];
    const float* w      = (const float*)d_in[1];
    const float* ln_g   = (const float*)d_in[2];
    const float* ln_b   = (const float*)d_in[3];
    const float* Wg     = (const float*)d_in[4];
    const float* bg     = (const float*)d_in[5];
    const float* Wb     = (const float*)d_in[6];
    const float* bb     = (const float*)d_in[7];
    const float* Wqkv   = (const float*)d_in[8];
    const float* bqkv   = (const float*)d_in[9];
    const float* Wp     = (const float*)d_in[10];
    const float* bp     = (const float*)d_in[11];
    float* out = (float*)d_out;

    float *p_qkv, *p_h1, *p_bqkv;
    __nv_bfloat16 *p_ahi, *p_alo, *p_bhi, *p_blo;
    cudaGetSymbolAddress((void**)&p_qkv, g_qkv);
    cudaGetSymbolAddress((void**)&p_h1, g_h1);
    cudaGetSymbolAddress((void**)&p_bqkv, g_bqkv);
    cudaGetSymbolAddress((void**)&p_ahi, g_Ahi);
    cudaGetSymbolAddress((void**)&p_alo, g_Alo);
    cudaGetSymbolAddress((void**)&p_bhi, g_Bhi);
    cudaGetSymbolAddress((void**)&p_blo, g_Blo);

    cudaFuncSetAttribute(flash_tc,
                         cudaFuncAttributeMaxDynamicSharedMemorySize, FLASH_SMEM);
    cudaFuncSetAttribute(gemm_mma,
                         cudaFuncAttributeMaxDynamicSharedMemorySize, GEMM_SMEM);

    // 1) gamma/beta + permuted qkv bias
    gamma_beta_kernel<<<32, 256>>>(w, Wg, bg, Wb, bb);
    permute_bias<<<12, 256>>>(bqkv);

    // 2) h = sln(hidden) -> bf16 hi/lo
    sln_kernel<<<M_, 256>>>(hidden, ln_g, ln_b, nullptr, p_ahi, p_alo, 0);

    // 3) qkv = h @ Wqkv^T + bqkv (row-permuted so cols = which*1024+h*64+d)
    cvt_split_permW<<<(QKV_ * D_) / 2048, 256>>>(Wqkv, p_bhi, p_blo);
    gemm_mma<<<dim3(QKV_ / 128, M_ / 128), 256, GEMM_SMEM>>>(
        p_ahi, p_alo, p_bhi, p_blo, p_bqkv, nullptr, p_qkv, M_, QKV_, D_);

    // 4) attention
    flash_tc<<<dim3(N_ / 128, B_ * H_), 256, FLASH_SMEM>>>(p_ahi, p_alo);

    // 5) h1 = attn @ Wp^T + bp + hidden
    cvt_split<<<(D_ * D_) / 2048, 256>>>(Wp, p_bhi, p_blo);
    gemm_mma<<<dim3(D_ / 128, M_ / 128), 256, GEMM_SMEM>>>(
        p_ahi, p_alo, p_bhi, p_blo, bp, hidden, p_h1, M_, D_, D_);

    // 6) out = sln(h1) + h1
    sln_kernel<<<M_, 256>>>(p_h1, ln_g, ln_b, out, nullptr, nullptr, 1);
}

// round 8
// speedup vs baseline: 2.3788x; 1.0837x over previous
#include <cuda_runtime.h>
#include <cuda_bf16.h>
#include <math.h>
#include <stdint.h>

// Shapes (fixed for this problem)
#define B_ 4
#define N_ 1024
#define D_ 1024
#define H_ 16
#define HD_ 64
#define M_ (B_ * N_)          // 4096 rows
#define QKV_ (3 * D_)         // 3072

// -------- scratch (no allocations allowed; __device__ globals) --------
__device__ float g_qkv[M_ * QKV_];    // qkv, layout [b,n][which*1024+h*64+d]
__device__ float g_h1[M_ * D_];
__device__ float g_gamma[B_ * D_];
__device__ float g_beta[B_ * D_];
__device__ float g_bqkv[QKV_];        // permuted qkv bias
// bf16 split buffers
__device__ __nv_bfloat16 g_Ahi[M_ * D_];
__device__ __nv_bfloat16 g_Alo[M_ * D_];
__device__ __nv_bfloat16 g_Bhi[QKV_ * D_];
__device__ __nv_bfloat16 g_Blo[QKV_ * D_];

__device__ __forceinline__ uint32_t smem_to_u32(const void* p) {
    uint32_t a;
    asm("{ .reg .u64 t; cvta.to.shared.u64 t, %1; cvt.u32.u64 %0, t; }"
        : "=r"(a) : "l"(p));
    return a;
}

// ===================================================================
// gamma/beta
// ===================================================================
__global__ __launch_bounds__(256) void gamma_beta_kernel(
    const float* __restrict__ w,
    const float* __restrict__ Wg, const float* __restrict__ bg,
    const float* __restrict__ Wb, const float* __restrict__ bb)
{
    int idx = blockIdx.x * 256 + threadIdx.x;
    int which = idx >> 12;
    int b = (idx >> 10) & 3;
    int d = idx & 1023;
    const float* Wrow = (which ? Wb : Wg) + (size_t)d * D_;
    const float* wr = w + b * D_;
    float acc = 0.f;
    #pragma unroll 4
    for (int k = 0; k < D_; k += 4) {
        float4 a = *(const float4*)&wr[k];
        float4 c = *(const float4*)&Wrow[k];
        acc += a.x * c.x + a.y * c.y + a.z * c.z + a.w * c.w;
    }
    if (which) g_beta[b * D_ + d]  = acc + bb[d];
    else       g_gamma[b * D_ + d] = acc + bg[d];
}

// ===================================================================
// split helper
// ===================================================================
__device__ __forceinline__ uint32_t split_pair(float f0, float f1, uint32_t& lo) {
    __nv_bfloat16 h0 = __float2bfloat16_rn(f0);
    __nv_bfloat16 h1 = __float2bfloat16_rn(f1);
    __nv_bfloat16 l0 = __float2bfloat16_rn(f0 - __bfloat162float(h0));
    __nv_bfloat16 l1 = __float2bfloat16_rn(f1 - __bfloat162float(h1));
    lo = (uint32_t)__bfloat16_as_ushort(l0) | ((uint32_t)__bfloat16_as_ushort(l1) << 16);
    return (uint32_t)__bfloat16_as_ushort(h0) | ((uint32_t)__bfloat16_as_ushort(h1) << 16);
}

// ===================================================================
// SLN. outf==null: write bf16 hi/lo split. else fp32 (+res).
// ===================================================================
__global__ __launch_bounds__(256) void sln_kernel(
    const float* __restrict__ x,
    const float* __restrict__ ln_g, const float* __restrict__ ln_b,
    float* __restrict__ outf,
    __nv_bfloat16* __restrict__ ohi, __nv_bfloat16* __restrict__ olo,
    int add_res)
{
    int row = blockIdx.x;
    int b = row >> 10;
    const float* xr = x + (size_t)row * D_;
    int t = threadIdx.x;

    float4 v = ((const float4*)xr)[t];
    float s  = v.x + v.y + v.z + v.w;
    float sq = v.x * v.x + v.y * v.y + v.z * v.z + v.w * v.w;
    #pragma unroll
    for (int o = 16; o; o >>= 1) {
        s  += __shfl_xor_sync(0xffffffffu, s, o);
        sq += __shfl_xor_sync(0xffffffffu, sq, o);
    }
    __shared__ float ss[8], ssq[8];
    int w = t >> 5, ln = t & 31;
    if (ln == 0) { ss[w] = s; ssq[w] = sq; }
    __syncthreads();
    s = 0.f; sq = 0.f;
    #pragma unroll
    for (int i = 0; i < 8; i++) { s += ss[i]; sq += ssq[i]; }

    float mu = s * (1.f / D_);
    float var = sq * (1.f / D_) - mu * mu;
    float rstd = rsqrtf(var + 1e-5f);

    float4 lg = ((const float4*)ln_g)[t];
    float4 lb = ((const float4*)ln_b)[t];
    float4 ga = ((const float4*)(g_gamma + b * D_))[t];
    float4 be = ((const float4*)(g_beta  + b * D_))[t];

    float4 r;
    r.x = ga.x * ((v.x - mu) * rstd * lg.x + lb.x) + be.x;
    r.y = ga.y * ((v.y - mu) * rstd * lg.y + lb.y) + be.y;
    r.z = ga.z * ((v.z - mu) * rstd * lg.z + lb.z) + be.z;
    r.w = ga.w * ((v.w - mu) * rstd * lg.w + lb.w) + be.w;
    if (add_res) { r.x += v.x; r.y += v.y; r.z += v.z; r.w += v.w; }
    if (outf) {
        ((float4*)(outf + (size_t)row * D_))[t] = r;
    } else {
        uint2 vh, vl;
        vh.x = split_pair(r.x, r.y, vl.x);
        vh.y = split_pair(r.z, r.w, vl.y);
        *(uint2*)(ohi + (size_t)row * D_ + t * 4) = vh;
        *(uint2*)(olo + (size_t)row * D_ + t * 4) = vl;
    }
}

// ===================================================================
// cvt_split (plain, for Wp)
// ===================================================================
__global__ __launch_bounds__(256) void cvt_split(
    const float* __restrict__ src,
    __nv_bfloat16* __restrict__ hi, __nv_bfloat16* __restrict__ lo)
{
    int i = (blockIdx.x * 256 + threadIdx.x) * 8;
    float4 a = *(const float4*)(src + i);
    float4 b = *(const float4*)(src + i + 4);
    uint4 vh, vl;
    vh.x = split_pair(a.x, a.y, vl.x);
    vh.y = split_pair(a.z, a.w, vl.y);
    vh.z = split_pair(b.x, b.y, vl.z);
    vh.w = split_pair(b.z, b.w, vl.w);
    *(uint4*)(hi + i) = vh;
    *(uint4*)(lo + i) = vl;
}

// ===================================================================
// cvt_split with qkv row permutation: src row h*192+d*3+wh -> wh*1024+h*64+d
// ===================================================================
__global__ __launch_bounds__(256) void cvt_split_permW(
    const float* __restrict__ src,
    __nv_bfloat16* __restrict__ hi, __nv_bfloat16* __restrict__ lo)
{
    int idx = (blockIdx.x * 256 + threadIdx.x) * 8;
    int row = idx >> 10, col = idx & 1023;
    int h = row / 192, rem = row % 192;
    int d = rem / 3, wh = rem % 3;
    size_t dst = ((size_t)(wh * 1024 + h * 64 + d) << 10) + col;
    float4 a = *(const float4*)(src + idx);
    float4 b = *(const float4*)(src + idx + 4);
    uint4 vh, vl;
    vh.x = split_pair(a.x, a.y, vl.x);
    vh.y = split_pair(a.z, a.w, vl.y);
    vh.z = split_pair(b.x, b.y, vl.z);
    vh.w = split_pair(b.z, b.w, vl.w);
    *(uint4*)(hi + dst) = vh;
    *(uint4*)(lo + dst) = vl;
}

__global__ void permute_bias(const float* __restrict__ b) {
    int r = blockIdx.x * 256 + threadIdx.x;
    if (r < QKV_) {
        int h = r / 192, rem = r % 192;
        int d = rem / 3, wh = rem % 3;
        g_bqkv[wh * 1024 + h * 64 + d] = b[r];
    }
}

// ===================================================================
// mma helpers
// ===================================================================
__device__ __forceinline__ void ldmx4(uint32_t* r, uint32_t addr) {
    asm volatile("ldmatrix.sync.aligned.m8n8.x4.shared.b16 {%0,%1,%2,%3}, [%4];"
                 : "=r"(r[0]), "=r"(r[1]), "=r"(r[2]), "=r"(r[3]) : "r"(addr));
}
__device__ __forceinline__ void ldmx2(uint32_t* r, uint32_t addr) {
    asm volatile("ldmatrix.sync.aligned.m8n8.x2.shared.b16 {%0,%1}, [%2];"
                 : "=r"(r[0]), "=r"(r[1]) : "r"(addr));
}
__device__ __forceinline__ void ldmx2t(uint32_t* r, uint32_t addr) {
    asm volatile("ldmatrix.sync.aligned.m8n8.x2.trans.shared.b16 {%0,%1}, [%2];"
                 : "=r"(r[0]), "=r"(r[1]) : "r"(addr));
}
__device__ __forceinline__ void mma16816(float* c, const uint32_t* a, const uint32_t* b) {
    asm volatile("mma.sync.aligned.m16n8k16.row.col.f32.bf16.bf16.f32 "
                 "{%0,%1,%2,%3}, {%4,%5,%6,%7}, {%8,%9}, {%0,%1,%2,%3};"
                 : "+f"(c[0]), "+f"(c[1]), "+f"(c[2]), "+f"(c[3])
                 : "r"(a[0]), "r"(a[1]), "r"(a[2]), "r"(a[3]), "r"(b[0]), "r"(b[1]));
}

// ===================================================================
// mma.sync bf16 GEMM, BK=32, 2-stage, 2 CTAs/SM (regs capped at 128).
// C[M,N] = A @ W^T + bias (+residual). CTA 128x128, 8 warps (2x4).
// ===================================================================
#define RS 40
#define MAT_ELEMS (128 * RS)
#define STAGE_ELEMS (4 * MAT_ELEMS)
#define GEMM_SMEM (2 * STAGE_ELEMS * 2)   // 81920 B -> 2 CTAs/SM

__global__ __launch_bounds__(256, 2) void gemm_mma(
    const __nv_bfloat16* __restrict__ Ahi, const __nv_bfloat16* __restrict__ Alo,
    const __nv_bfloat16* __restrict__ Bhi, const __nv_bfloat16* __restrict__ Blo,
    const float* __restrict__ bias, const float* __restrict__ residual,
    float* __restrict__ C, int M, int N, int K)
{
    extern __shared__ __nv_bfloat16 smb[];
    uint32_t sbase = smem_to_u32(smb);
    int tid = threadIdx.x, wid = tid >> 5, lane = tid & 31;
    int m0 = blockIdx.y * 128, n0 = blockIdx.x * 128;
    int wm = wid >> 2, wn = wid & 3;

    float acc[4][4][4];
    #pragma unroll
    for (int i = 0; i < 4; i++)
        #pragma unroll
        for (int j = 0; j < 4; j++)
            #pragma unroll
            for (int c = 0; c < 4; c++) acc[i][j][c] = 0.f;

    const int nch = K >> 5;

    auto load_stage = [&](int ch, int s) {
        int kk = ch << 5;
        #pragma unroll
        for (int t = 0; t < 8; t++) {
            int idx = t * 256 + tid;
            int mat = idx >> 9;
            int row = (idx >> 2) & 127;
            int seg = idx & 3;
            const __nv_bfloat16* src = (mat == 0) ? Ahi : (mat == 1) ? Alo
                                     : (mat == 2) ? Bhi : Blo;
            int rb = (mat < 2) ? m0 : n0;
            const __nv_bfloat16* g = src + (size_t)(rb + row) * K + kk + seg * 8;
            uint32_t dst = sbase + (uint32_t)((s * STAGE_ELEMS + mat * MAT_ELEMS
                                               + row * RS + seg * 8) * 2);
            asm volatile("cp.async.cg.shared.global [%0], [%1], 16;"
                         :: "r"(dst), "l"(g) : "memory");
        }
        asm volatile("cp.async.commit_group;" ::: "memory");
    };

    auto compute_stage = [&](int s) {
        uint32_t stage_b = sbase + (uint32_t)(s * STAGE_ELEMS * 2);
        #pragma unroll
        for (int ks = 0; ks < 2; ks++) {
            uint32_t ahi[4][4], alo[4][4];
            int arow = wm * 64 + (lane & 15);
            int acol = ks * 16 + (lane >> 4) * 8;
            #pragma unroll
            for (int i = 0; i < 4; i++) {
                uint32_t off = (uint32_t)(((arow + i * 16) * RS + acol) * 2);
                ldmx4(ahi[i], stage_b + 0 * MAT_ELEMS * 2 + off);
                ldmx4(alo[i], stage_b + 1 * MAT_ELEMS * 2 + off);
            }
            uint32_t bhi[4][2], blo[4][2];
            int bl = lane & 15;
            int brow = wn * 32 + (bl & 7);
            int bcol = ks * 16 + (bl >> 3) * 8;
            #pragma unroll
            for (int j = 0; j < 4; j++) {
                uint32_t off = (uint32_t)(((brow + j * 8) * RS + bcol) * 2);
                ldmx2(bhi[j], stage_b + 2 * MAT_ELEMS * 2 + off);
                ldmx2(blo[j], stage_b + 3 * MAT_ELEMS * 2 + off);
            }
            #pragma unroll
            for (int i = 0; i < 4; i++)
                #pragma unroll
                for (int j = 0; j < 4; j++) {
                    mma16816(acc[i][j], ahi[i], bhi[j]);
                    mma16816(acc[i][j], ahi[i], blo[j]);
                    mma16816(acc[i][j], alo[i], bhi[j]);
                }
        }
    };

    load_stage(0, 0);
    for (int ch = 0; ch < nch; ch++) {
        if (ch + 1 < nch) {
            load_stage(ch + 1, (ch + 1) & 1);
            asm volatile("cp.async.wait_group 1;" ::: "memory");
        } else {
            asm volatile("cp.async.wait_group 0;" ::: "memory");
        }
        __syncthreads();
        compute_stage(ch & 1);
        __syncthreads();
    }

    int r = lane >> 2, cp2 = (lane & 3) * 2;
    #pragma unroll
    for (int i = 0; i < 4; i++) {
        int row0 = m0 + wm * 64 + i * 16 + r;
        #pragma unroll
        for (int j = 0; j < 4; j++) {
            int col = n0 + wn * 32 + j * 8 + cp2;
            float2 bv = *(const float2*)(bias + col);
            float2 o0, o1;
            o0.x = acc[i][j][0] + bv.x; o0.y = acc[i][j][1] + bv.y;
            o1.x = acc[i][j][2] + bv.x; o1.y = acc[i][j][3] + bv.y;
            if (residual) {
                float2 r0 = *(const float2*)(residual + (size_t)row0 * N + col);
                float2 r1 = *(const float2*)(residual + (size_t)(row0 + 8) * N + col);
                o0.x += r0.x; o0.y += r0.y;
                o1.x += r1.x; o1.y += r1.y;
            }
            *(float2*)(C + (size_t)row0 * N + col) = o0;
            *(float2*)(C + (size_t)(row0 + 8) * N + col) = o1;
        }
    }
}

// ===================================================================
// Tensor-core flash attention, coalesced qkv layout, 2 CTAs/SM.
// ===================================================================
#define RS2 72
#define F_QHI 0
#define F_QLO (128 * RS2)
#define F_KHI (2 * 128 * RS2)
#define F_KLO (F_KHI + 64 * RS2)
#define F_VHI (F_KLO + 64 * RS2)
#define F_VLO (F_VHI + 64 * RS2)
#define FLASH_SMEM ((F_VLO + 64 * RS2) * 2)   // 73728 B -> 2 CTAs/SM

__global__ __launch_bounds__(256, 2) void flash_tc(
    __nv_bfloat16* __restrict__ ohi, __nv_bfloat16* __restrict__ olo)
{
    extern __shared__ __nv_bfloat16 smb[];
    uint32_t sbase = smem_to_u32(smb);
    int tid = threadIdx.x, wid = tid >> 5, lane = tid & 31;
    int bh = blockIdx.y;
    int b = bh >> 4, h = bh & 15;
    int q0 = blockIdx.x * 128;
    const float* qkv = g_qkv;
    size_t rowbase = (size_t)(b * N_) * QKV_ + h * 64;

    // Q tile 128x64, coalesced float4
    #pragma unroll
    for (int it = 0; it < 8; it++) {
        int i = it * 256 + tid;
        int q = i >> 4, dg = (i & 15) * 4;
        float4 v = *(const float4*)(qkv + rowbase + (size_t)(q0 + q) * QKV_ + dg);
        uint32_t lo0, lo1;
        uint32_t hi0 = split_pair(v.x, v.y, lo0);
        uint32_t hi1 = split_pair(v.z, v.w, lo1);
        uint32_t o = q * RS2 + dg;
        *(uint32_t*)(smb + F_QHI + o) = hi0;
        *(uint32_t*)(smb + F_QHI + o + 2) = hi1;
        *(uint32_t*)(smb + F_QLO + o) = lo0;
        *(uint32_t*)(smb + F_QLO + o + 2) = lo1;
    }

    float mr0 = -1e30f, mr1 = -1e30f, l0 = 0.f, l1 = 0.f;
    float O[8][4] = {};

    for (int kb = 0; kb < N_; kb += 64) {
        __syncthreads();
        #pragma unroll
        for (int it = 0; it < 4; it++) {
            int i = it * 256 + tid;
            int r = i >> 4, dg = (i & 15) * 4;
            size_t p = rowbase + (size_t)(kb + r) * QKV_ + dg;
            float4 kv = *(const float4*)(qkv + p + 1024);
            float4 vv = *(const float4*)(qkv + p + 2048);
            uint32_t lo0, lo1;
            uint32_t hi0 = split_pair(kv.x, kv.y, lo0);
            uint32_t hi1 = split_pair(kv.z, kv.w, lo1);
            uint32_t o = r * RS2 + dg;
            *(uint32_t*)(smb + F_KHI + o) = hi0;
            *(uint32_t*)(smb + F_KHI + o + 2) = hi1;
            *(uint32_t*)(smb + F_KLO + o) = lo0;
            *(uint32_t*)(smb + F_KLO + o + 2) = lo1;
            hi0 = split_pair(vv.x, vv.y, lo0);
            hi1 = split_pair(vv.z, vv.w, lo1);
            *(uint32_t*)(smb + F_VHI + o) = hi0;
            *(uint32_t*)(smb + F_VHI + o + 2) = hi1;
            *(uint32_t*)(smb + F_VLO + o) = lo0;
            *(uint32_t*)(smb + F_VLO + o + 2) = lo1;
        }
        __syncthreads();

        // ---- S = Q K^T ----
        float S[8][4];
        #pragma unroll
        for (int j = 0; j < 8; j++)
            #pragma unroll
            for (int c = 0; c < 4; c++) S[j][c] = 0.f;

        #pragma unroll
        for (int ks = 0; ks < 4; ks++) {
            uint32_t qh[4], ql[4];
            uint32_t aoff = (uint32_t)(((wid * 16 + (lane & 15)) * RS2
                                        + ks * 16 + (lane >> 4) * 8) * 2);
            ldmx4(qh, sbase + F_QHI * 2 + aoff);
            ldmx4(ql, sbase + F_QLO * 2 + aoff);
            #pragma unroll
            for (int j = 0; j < 8; j++) {
                uint32_t kh[2], kl[2];
                uint32_t boff = (uint32_t)(((j * 8 + (lane & 7)) * RS2
                                            + ks * 16 + ((lane & 15) >> 3) * 8) * 2);
                ldmx2(kh, sbase + F_KHI * 2 + boff);
                ldmx2(kl, sbase + F_KLO * 2 + boff);
                mma16816(S[j], qh, kh);
                mma16816(S[j], qh, kl);
                mma16816(S[j], ql, kh);
            }
        }

        // ---- online softmax ----
        float rm0 = -1e30f, rm1 = -1e30f;
        #pragma unroll
        for (int j = 0; j < 8; j++) {
            rm0 = fmaxf(rm0, fmaxf(S[j][0], S[j][1]));
            rm1 = fmaxf(rm1, fmaxf(S[j][2], S[j][3]));
        }
        rm0 = fmaxf(rm0, __shfl_xor_sync(0xffffffffu, rm0, 1));
        rm0 = fmaxf(rm0, __shfl_xor_sync(0xffffffffu, rm0, 2));
        rm1 = fmaxf(rm1, __shfl_xor_sync(0xffffffffu, rm1, 1));
        rm1 = fmaxf(rm1, __shfl_xor_sync(0xffffffffu, rm1, 2));
        float mn0 = fmaxf(mr0, rm0), mn1 = fmaxf(mr1, rm1);
        float sc0 = __expf(mr0 - mn0), sc1 = __expf(mr1 - mn1);
        float rs0 = 0.f, rs1 = 0.f;
        #pragma unroll
        for (int j = 0; j < 8; j++) {
            S[j][0] = __expf(S[j][0] - mn0);
            S[j][1] = __expf(S[j][1] - mn0);
            S[j][2] = __expf(S[j][2] - mn1);
            S[j][3] = __expf(S[j][3] - mn1);
            rs0 += S[j][0] + S[j][1];
            rs1 += S[j][2] + S[j][3];
        }
        rs0 += __shfl_xor_sync(0xffffffffu, rs0, 1);
        rs0 += __shfl_xor_sync(0xffffffffu, rs0, 2);
        rs1 += __shfl_xor_sync(0xffffffffu, rs1, 1);
        rs1 += __shfl_xor_sync(0xffffffffu, rs1, 2);
        l0 = l0 * sc0 + rs0;
        l1 = l1 * sc1 + rs1;
        mr0 = mn0; mr1 = mn1;
        #pragma unroll
        for (int j = 0; j < 8; j++) {
            O[j][0] *= sc0; O[j][1] *= sc0;
            O[j][2] *= sc1; O[j][3] *= sc1;
        }

        // ---- O += P V ----
        #pragma unroll
        for (int t = 0; t < 4; t++) {
            uint32_t ph[4], pl[4];
            ph[0] = split_pair(S[2 * t][0],     S[2 * t][1],     pl[0]);
            ph[1] = split_pair(S[2 * t][2],     S[2 * t][3],     pl[1]);
            ph[2] = split_pair(S[2 * t + 1][0], S[2 * t + 1][1], pl[2]);
            ph[3] = split_pair(S[2 * t + 1][2], S[2 * t + 1][3], pl[3]);
            #pragma unroll
            for (int dt = 0; dt < 8; dt++) {
                uint32_t vh[2], vl[2];
                uint32_t voff = (uint32_t)(((t * 16 + (lane & 15)) * RS2 + dt * 8) * 2);
                ldmx2t(vh, sbase + F_VHI * 2 + voff);
                ldmx2t(vl, sbase + F_VLO * 2 + voff);
                mma16816(O[dt], ph, vh);
                mma16816(O[dt], ph, vl);
                mma16816(O[dt], pl, vh);
            }
        }
    }

    // ---- epilogue ----
    float inv0 = 1.f / (l0 * 32.f), inv1 = 1.f / (l1 * 32.f);
    int r = lane >> 2, c2 = (lane & 3) * 2;
    int q = q0 + wid * 16 + r;
    #pragma unroll
    for (int dt = 0; dt < 8; dt++) {
        int col = h * 64 + dt * 8 + c2;
        uint32_t lo0, lo1;
        uint32_t hi0 = split_pair(O[dt][0] * inv0, O[dt][1] * inv0, lo0);
        uint32_t hi1 = split_pair(O[dt][2] * inv1, O[dt][3] * inv1, lo1);
        size_t off0 = (size_t)(b * N_ + q) * D_ + col;
        size_t off1 = (size_t)(b * N_ + q + 8) * D_ + col;
        *(uint32_t*)(ohi + off0) = hi0;
        *(uint32_t*)(olo + off0) = lo0;
        *(uint32_t*)(ohi + off1) = hi1;
        *(uint32_t*)(olo + off1) = lo1;
    }
}

// ===================================================================
extern "C" void kernel_launch(void* const* d_in, const int* in_sizes, int n_in,
                              void* d_out, int out_size)
{
    const float* hidden = (const float*)d_in[0];
    const float* w      = (const float*)d_in[1];
    const float* ln_g   = (const float*)d_in[2];
    const float* ln_b   = (const float*)d_in[3];
    const float* Wg     = (const float*)d_in[4];
    const float* bg     = (const float*)d_in[5];
    const float* Wb     = (const float*)d_in[6];
    const float* bb     = (const float*)d_in[7];
    const float* Wqkv   = (const float*)d_in[8];
    const float* bqkv   = (const float*)d_in[9];
    const float* Wp     = (const float*)d_in[10];
    const float* bp     = (const float*)d_in[11];
    float* out = (float*)d_out;

    float *p_qkv, *p_h1, *p_bqkv;
    __nv_bfloat16 *p_ahi, *p_alo, *p_bhi, *p_blo;
    cudaGetSymbolAddress((void**)&p_qkv, g_qkv);
    cudaGetSymbolAddress((void**)&p_h1, g_h1);
    cudaGetSymbolAddress((void**)&p_bqkv, g_bqkv);
    cudaGetSymbolAddress((void**)&p_ahi, g_Ahi);
    cudaGetSymbolAddress((void**)&p_alo, g_Alo);
    cudaGetSymbolAddress((void**)&p_bhi, g_Bhi);
    cudaGetSymbolAddress((void**)&p_blo, g_Blo);

    cudaFuncSetAttribute(flash_tc,
                         cudaFuncAttributeMaxDynamicSharedMemorySize, FLASH_SMEM);
    cudaFuncSetAttribute(gemm_mma,
                         cudaFuncAttributeMaxDynamicSharedMemorySize, GEMM_SMEM);

    // 1) gamma/beta + permuted qkv bias
    gamma_beta_kernel<<<32, 256>>>(w, Wg, bg, Wb, bb);
    permute_bias<<<12, 256>>>(bqkv);

    // 2) h = sln(hidden) -> bf16 hi/lo
    sln_kernel<<<M_, 256>>>(hidden, ln_g, ln_b, nullptr, p_ahi, p_alo, 0);

    // 3) qkv = h @ Wqkv^T + bqkv (permuted cols)
    cvt_split_permW<<<(QKV_ * D_) / 2048, 256>>>(Wqkv, p_bhi, p_blo);
    gemm_mma<<<dim3(QKV_ / 128, M_ / 128), 256, GEMM_SMEM>>>(
        p_ahi, p_alo, p_bhi, p_blo, p_bqkv, nullptr, p_qkv, M_, QKV_, D_);

    // 4) attention
    flash_tc<<<dim3(N_ / 128, B_ * H_), 256, FLASH_SMEM>>>(p_ahi, p_alo);

    // 5) h1 = attn @ Wp^T + bp + hidden
    cvt_split<<<(D_ * D_) / 2048, 256>>>(Wp, p_bhi, p_blo);
    gemm_mma<<<dim3(D_ / 128, M_ / 128), 256, GEMM_SMEM>>>(
        p_ahi, p_alo, p_bhi, p_blo, bp, hidden, p_h1, M_, D_, D_);

    // 6) out = sln(h1) + h1
    sln_kernel<<<M_, 256>>>(p_h1, ln_g, ln_b, out, nullptr, nullptr, 1);
}

// round 11
// speedup vs baseline: 5.0087x; 2.1055x over previous
#include <cuda_runtime.h>
#include <cuda_fp16.h>
#include <math.h>
#include <stdint.h>

// Shapes (fixed)
#define B_ 4
#define N_ 1024
#define D_ 1024
#define H_ 16
#define HD_ 64
#define M_ (B_ * N_)
#define QKV_ (3 * D_)

// -------- scratch --------
__device__ float g_qkv[M_ * QKV_];    // qkv, layout [b,n][which*1024+h*64+d]
__device__ float g_h1[M_ * D_];
__device__ float g_gamma[B_ * D_];
__device__ float g_beta[B_ * D_];
__device__ float g_bqkv[QKV_];
__device__ __half g_Ah[M_ * D_];      // fp16 activations
__device__ __half g_Bh[QKV_ * D_];    // fp16 weights

__device__ __forceinline__ uint32_t smem_to_u32(const void* p) {
    uint32_t a;
    asm("{ .reg .u64 t; cvta.to.shared.u64 t, %1; cvt.u32.u64 %0, t; }"
        : "=r"(a) : "l"(p));
    return a;
}
__device__ __forceinline__ uint32_t pack_h2(float a, float b) {
    __half2 h = __floats2half2_rn(a, b);
    return *(uint32_t*)&h;
}

// ===================================================================
// gamma/beta
// ===================================================================
__global__ __launch_bounds__(256) void gamma_beta_kernel(
    const float* __restrict__ w,
    const float* __restrict__ Wg, const float* __restrict__ bg,
    const float* __restrict__ Wb, const float* __restrict__ bb)
{
    int idx = blockIdx.x * 256 + threadIdx.x;
    int which = idx >> 12;
    int b = (idx >> 10) & 3;
    int d = idx & 1023;
    const float* Wrow = (which ? Wb : Wg) + (size_t)d * D_;
    const float* wr = w + b * D_;
    float acc = 0.f;
    #pragma unroll 4
    for (int k = 0; k < D_; k += 4) {
        float4 a = *(const float4*)&wr[k];
        float4 c = *(const float4*)&Wrow[k];
        acc += a.x * c.x + a.y * c.y + a.z * c.z + a.w * c.w;
    }
    if (which) g_beta[b * D_ + d]  = acc + bb[d];
    else       g_gamma[b * D_ + d] = acc + bg[d];
}

// ===================================================================
// SLN. oh==null: write fp32 (+res). else write fp16.
// ===================================================================
__global__ __launch_bounds__(256) void sln_kernel(
    const float* __restrict__ x,
    const float* __restrict__ ln_g, const float* __restrict__ ln_b,
    float* __restrict__ outf, __half* __restrict__ oh, int add_res)
{
    int row = blockIdx.x;
    int b = row >> 10;
    const float* xr = x + (size_t)row * D_;
    int t = threadIdx.x;

    float4 v = ((const float4*)xr)[t];
    float s  = v.x + v.y + v.z + v.w;
    float sq = v.x * v.x + v.y * v.y + v.z * v.z + v.w * v.w;
    #pragma unroll
    for (int o = 16; o; o >>= 1) {
        s  += __shfl_xor_sync(0xffffffffu, s, o);
        sq += __shfl_xor_sync(0xffffffffu, sq, o);
    }
    __shared__ float ss[8], ssq[8];
    int w = t >> 5, ln = t & 31;
    if (ln == 0) { ss[w] = s; ssq[w] = sq; }
    __syncthreads();
    s = 0.f; sq = 0.f;
    #pragma unroll
    for (int i = 0; i < 8; i++) { s += ss[i]; sq += ssq[i]; }

    float mu = s * (1.f / D_);
    float var = sq * (1.f / D_) - mu * mu;
    float rstd = rsqrtf(var + 1e-5f);

    float4 lg = ((const float4*)ln_g)[t];
    float4 lb = ((const float4*)ln_b)[t];
    float4 ga = ((const float4*)(g_gamma + b * D_))[t];
    float4 be = ((const float4*)(g_beta  + b * D_))[t];

    float4 r;
    r.x = ga.x * ((v.x - mu) * rstd * lg.x + lb.x) + be.x;
    r.y = ga.y * ((v.y - mu) * rstd * lg.y + lb.y) + be.y;
    r.z = ga.z * ((v.z - mu) * rstd * lg.z + lb.z) + be.z;
    r.w = ga.w * ((v.w - mu) * rstd * lg.w + lb.w) + be.w;
    if (add_res) { r.x += v.x; r.y += v.y; r.z += v.z; r.w += v.w; }
    if (outf) {
        ((float4*)(outf + (size_t)row * D_))[t] = r;
    } else {
        uint2 vh;
        vh.x = pack_h2(r.x, r.y);
        vh.y = pack_h2(r.z, r.w);
        *(uint2*)(oh + (size_t)row * D_ + t * 4) = vh;
    }
}

// ===================================================================
// cvt to fp16 (plain, for Wp)
// ===================================================================
__global__ __launch_bounds__(256) void cvt_half(
    const float* __restrict__ src, __half* __restrict__ dst)
{
    int i = (blockIdx.x * 256 + threadIdx.x) * 8;
    float4 a = *(const float4*)(src + i);
    float4 b = *(const float4*)(src + i + 4);
    uint4 vh;
    vh.x = pack_h2(a.x, a.y);
    vh.y = pack_h2(a.z, a.w);
    vh.z = pack_h2(b.x, b.y);
    vh.w = pack_h2(b.z, b.w);
    *(uint4*)(dst + i) = vh;
}

// ===================================================================
// cvt fp16 with qkv row permutation: h*192+d*3+wh -> wh*1024+h*64+d
// ===================================================================
__global__ __launch_bounds__(256) void cvt_half_permW(
    const float* __restrict__ src, __half* __restrict__ dst)
{
    int idx = (blockIdx.x * 256 + threadIdx.x) * 8;
    int row = idx >> 10, col = idx & 1023;
    int h = row / 192, rem = row % 192;
    int d = rem / 3, wh = rem % 3;
    size_t dsti = ((size_t)(wh * 1024 + h * 64 + d) << 10) + col;
    float4 a = *(const float4*)(src + idx);
    float4 b = *(const float4*)(src + idx + 4);
    uint4 vh;
    vh.x = pack_h2(a.x, a.y);
    vh.y = pack_h2(a.z, a.w);
    vh.z = pack_h2(b.x, b.y);
    vh.w = pack_h2(b.z, b.w);
    *(uint4*)(dst + dsti) = vh;
}

__global__ void permute_bias(const float* __restrict__ b) {
    int r = blockIdx.x * 256 + threadIdx.x;
    if (r < QKV_) {
        int h = r / 192, rem = r % 192;
        int d = rem / 3, wh = rem % 3;
        g_bqkv[wh * 1024 + h * 64 + d] = b[r];
    }
}

// ===================================================================
// mma helpers (fp16)
// ===================================================================
__device__ __forceinline__ void ldmx4(uint32_t* r, uint32_t addr) {
    asm volatile("ldmatrix.sync.aligned.m8n8.x4.shared.b16 {%0,%1,%2,%3}, [%4];"
                 : "=r"(r[0]), "=r"(r[1]), "=r"(r[2]), "=r"(r[3]) : "r"(addr));
}
__device__ __forceinline__ void ldmx2(uint32_t* r, uint32_t addr) {
    asm volatile("ldmatrix.sync.aligned.m8n8.x2.shared.b16 {%0,%1}, [%2];"
                 : "=r"(r[0]), "=r"(r[1]) : "r"(addr));
}
__device__ __forceinline__ void ldmx2t(uint32_t* r, uint32_t addr) {
    asm volatile("ldmatrix.sync.aligned.m8n8.x2.trans.shared.b16 {%0,%1}, [%2];"
                 : "=r"(r[0]), "=r"(r[1]) : "r"(addr));
}
__device__ __forceinline__ void mmaf16(float* c, const uint32_t* a, const uint32_t* b) {
    asm volatile("mma.sync.aligned.m16n8k16.row.col.f32.f16.f16.f32 "
                 "{%0,%1,%2,%3}, {%4,%5,%6,%7}, {%8,%9}, {%0,%1,%2,%3};"
                 : "+f"(c[0]), "+f"(c[1]), "+f"(c[2]), "+f"(c[3])
                 : "r"(a[0]), "r"(a[1]), "r"(a[2]), "r"(a[3]), "r"(b[0]), "r"(b[1]));
}

// ===================================================================
// fp16 GEMM: C[M,N] = A @ W^T + bias (+residual). CTA 128x128, BK=64,
// 2-stage cp.async, 8 warps (2x4), 2 CTAs/SM.
// ===================================================================
#define RSG 72
#define MAT_ELEMS (128 * RSG)           // 9216
#define STAGE_ELEMS (2 * MAT_ELEMS)     // 18432
#define GEMM_SMEM (2 * STAGE_ELEMS * 2) // 73728 B -> 2 CTAs/SM

__global__ __launch_bounds__(256, 2) void gemm_mma(
    const __half* __restrict__ A, const __half* __restrict__ Wt,
    const float* __restrict__ bias, const float* __restrict__ residual,
    float* __restrict__ C, int M, int N, int K)
{
    extern __shared__ __half smh[];
    uint32_t sbase = smem_to_u32(smh);
    int tid = threadIdx.x, wid = tid >> 5, lane = tid & 31;
    int m0 = blockIdx.y * 128, n0 = blockIdx.x * 128;
    int wm = wid >> 2, wn = wid & 3;

    float acc[4][4][4];
    #pragma unroll
    for (int i = 0; i < 4; i++)
        #pragma unroll
        for (int j = 0; j < 4; j++)
            #pragma unroll
            for (int c = 0; c < 4; c++) acc[i][j][c] = 0.f;

    const int nch = K >> 6;   // BK=64

    auto load_stage = [&](int ch, int s) {
        int kk = ch << 6;
        #pragma unroll
        for (int t = 0; t < 8; t++) {
            int idx = t * 256 + tid;        // 0..2047
            int mat = idx >> 10;            // 0..1
            int row = (idx >> 3) & 127;
            int seg = idx & 7;
            const __half* src = mat ? Wt : A;
            int rb = mat ? n0 : m0;
            const __half* g = src + (size_t)(rb + row) * K + kk + seg * 8;
            uint32_t dst = sbase + (uint32_t)((s * STAGE_ELEMS + mat * MAT_ELEMS
                                               + row * RSG + seg * 8) * 2);
            asm volatile("cp.async.cg.shared.global [%0], [%1], 16;"
                         :: "r"(dst), "l"(g) : "memory");
        }
        asm volatile("cp.async.commit_group;" ::: "memory");
    };

    auto compute_stage = [&](int s) {
        uint32_t stage_b = sbase + (uint32_t)(s * STAGE_ELEMS * 2);
        #pragma unroll
        for (int ks = 0; ks < 4; ks++) {
            uint32_t af[4][4];
            int arow = wm * 64 + (lane & 15);
            int acol = ks * 16 + (lane >> 4) * 8;
            #pragma unroll
            for (int i = 0; i < 4; i++) {
                uint32_t off = (uint32_t)(((arow + i * 16) * RSG + acol) * 2);
                ldmx4(af[i], stage_b + off);
            }
            uint32_t bf[4][2];
            int bl = lane & 15;
            int brow = wn * 32 + (bl & 7);
            int bcol = ks * 16 + (bl >> 3) * 8;
            #pragma unroll
            for (int j = 0; j < 4; j++) {
                uint32_t off = (uint32_t)(((brow + j * 8) * RSG + bcol) * 2);
                ldmx2(bf[j], stage_b + MAT_ELEMS * 2 + off);
            }
            #pragma unroll
            for (int i = 0; i < 4; i++)
                #pragma unroll
                for (int j = 0; j < 4; j++)
                    mmaf16(acc[i][j], af[i], bf[j]);
        }
    };

    load_stage(0, 0);
    for (int ch = 0; ch < nch; ch++) {
        if (ch + 1 < nch) {
            load_stage(ch + 1, (ch + 1) & 1);
            asm volatile("cp.async.wait_group 1;" ::: "memory");
        } else {
            asm volatile("cp.async.wait_group 0;" ::: "memory");
        }
        __syncthreads();
        compute_stage(ch & 1);
        __syncthreads();
    }

    int r = lane >> 2, cp2 = (lane & 3) * 2;
    #pragma unroll
    for (int i = 0; i < 4; i++) {
        int row0 = m0 + wm * 64 + i * 16 + r;
        #pragma unroll
        for (int j = 0; j < 4; j++) {
            int col = n0 + wn * 32 + j * 8 + cp2;
            float2 bv = *(const float2*)(bias + col);
            float2 o0, o1;
            o0.x = acc[i][j][0] + bv.x; o0.y = acc[i][j][1] + bv.y;
            o1.x = acc[i][j][2] + bv.x; o1.y = acc[i][j][3] + bv.y;
            if (residual) {
                float2 r0 = *(const float2*)(residual + (size_t)row0 * N + col);
                float2 r1 = *(const float2*)(residual + (size_t)(row0 + 8) * N + col);
                o0.x += r0.x; o0.y += r0.y;
                o1.x += r1.x; o1.y += r1.y;
            }
            *(float2*)(C + (size_t)row0 * N + col) = o0;
            *(float2*)(C + (size_t)(row0 + 8) * N + col) = o1;
        }
    }
}

// ===================================================================
// fp16 flash attention, coalesced qkv layout. Q tile 128, key blk 64.
// 8 warps x 16 q-rows. fp32 softmax/accum. Output -> fp16 g_Ah.
// ===================================================================
#define RS2 72
#define F_Q 0
#define F_K (128 * RS2)
#define F_V (F_K + 64 * RS2)
#define FLASH_SMEM ((F_V + 64 * RS2) * 2)   // 36864 B

__global__ __launch_bounds__(256, 2) void flash_tc(__half* __restrict__ oh)
{
    extern __shared__ __half smh[];
    uint32_t sbase = smem_to_u32(smh);
    int tid = threadIdx.x, wid = tid >> 5, lane = tid & 31;
    int bh = blockIdx.y;
    int b = bh >> 4, h = bh & 15;
    int q0 = blockIdx.x * 128;
    const float* qkv = g_qkv;
    size_t rowbase = (size_t)(b * N_) * QKV_ + h * 64;

    // Q tile 128x64
    #pragma unroll
    for (int it = 0; it < 8; it++) {
        int i = it * 256 + tid;
        int q = i >> 4, dg = (i & 15) * 4;
        float4 v = *(const float4*)(qkv + rowbase + (size_t)(q0 + q) * QKV_ + dg);
        uint32_t o = q * RS2 + dg;
        *(uint32_t*)(smh + F_Q + o) = pack_h2(v.x, v.y);
        *(uint32_t*)(smh + F_Q + o + 2) = pack_h2(v.z, v.w);
    }

    float mr0 = -1e30f, mr1 = -1e30f, l0 = 0.f, l1 = 0.f;
    float O[8][4] = {};

    for (int kb = 0; kb < N_; kb += 64) {
        __syncthreads();
        #pragma unroll
        for (int it = 0; it < 4; it++) {
            int i = it * 256 + tid;
            int r = i >> 4, dg = (i & 15) * 4;
            size_t p = rowbase + (size_t)(kb + r) * QKV_ + dg;
            float4 kv = *(const float4*)(qkv + p + 1024);
            float4 vv = *(const float4*)(qkv + p + 2048);
            uint32_t o = r * RS2 + dg;
            *(uint32_t*)(smh + F_K + o) = pack_h2(kv.x, kv.y);
            *(uint32_t*)(smh + F_K + o + 2) = pack_h2(kv.z, kv.w);
            *(uint32_t*)(smh + F_V + o) = pack_h2(vv.x, vv.y);
            *(uint32_t*)(smh + F_V + o + 2) = pack_h2(vv.z, vv.w);
        }
        __syncthreads();

        // ---- S = Q K^T ----
        float S[8][4];
        #pragma unroll
        for (int j = 0; j < 8; j++)
            #pragma unroll
            for (int c = 0; c < 4; c++) S[j][c] = 0.f;

        #pragma unroll
        for (int ks = 0; ks < 4; ks++) {
            uint32_t qf[4];
            uint32_t aoff = (uint32_t)(((wid * 16 + (lane & 15)) * RS2
                                        + ks * 16 + (lane >> 4) * 8) * 2);
            ldmx4(qf, sbase + F_Q * 2 + aoff);
            #pragma unroll
            for (int j = 0; j < 8; j++) {
                uint32_t kf[2];
                uint32_t boff = (uint32_t)(((j * 8 + (lane & 7)) * RS2
                                            + ks * 16 + ((lane & 15) >> 3) * 8) * 2);
                ldmx2(kf, sbase + F_K * 2 + boff);
                mmaf16(S[j], qf, kf);
            }
        }

        // ---- online softmax ----
        float rm0 = -1e30f, rm1 = -1e30f;
        #pragma unroll
        for (int j = 0; j < 8; j++) {
            rm0 = fmaxf(rm0, fmaxf(S[j][0], S[j][1]));
            rm1 = fmaxf(rm1, fmaxf(S[j][2], S[j][3]));
        }
        rm0 = fmaxf(rm0, __shfl_xor_sync(0xffffffffu, rm0, 1));
        rm0 = fmaxf(rm0, __shfl_xor_sync(0xffffffffu, rm0, 2));
        rm1 = fmaxf(rm1, __shfl_xor_sync(0xffffffffu, rm1, 1));
        rm1 = fmaxf(rm1, __shfl_xor_sync(0xffffffffu, rm1, 2));
        float mn0 = fmaxf(mr0, rm0), mn1 = fmaxf(mr1, rm1);
        float sc0 = __expf(mr0 - mn0), sc1 = __expf(mr1 - mn1);
        float rs0 = 0.f, rs1 = 0.f;
        #pragma unroll
        for (int j = 0; j < 8; j++) {
            S[j][0] = __expf(S[j][0] - mn0);
            S[j][1] = __expf(S[j][1] - mn0);
            S[j][2] = __expf(S[j][2] - mn1);
            S[j][3] = __expf(S[j][3] - mn1);
            rs0 += S[j][0] + S[j][1];
            rs1 += S[j][2] + S[j][3];
        }
        rs0 += __shfl_xor_sync(0xffffffffu, rs0, 1);
        rs0 += __shfl_xor_sync(0xffffffffu, rs0, 2);
        rs1 += __shfl_xor_sync(0xffffffffu, rs1, 1);
        rs1 += __shfl_xor_sync(0xffffffffu, rs1, 2);
        l0 = l0 * sc0 + rs0;
        l1 = l1 * sc1 + rs1;
        mr0 = mn0; mr1 = mn1;
        #pragma unroll
        for (int j = 0; j < 8; j++) {
            O[j][0] *= sc0; O[j][1] *= sc0;
            O[j][2] *= sc1; O[j][3] *= sc1;
        }

        // ---- O += P V ----
        #pragma unroll
        for (int t = 0; t < 4; t++) {
            uint32_t pf[4];
            pf[0] = pack_h2(S[2 * t][0],     S[2 * t][1]);
            pf[1] = pack_h2(S[2 * t][2],     S[2 * t][3]);
            pf[2] = pack_h2(S[2 * t + 1][0], S[2 * t + 1][1]);
            pf[3] = pack_h2(S[2 * t + 1][2], S[2 * t + 1][3]);
            #pragma unroll
            for (int dt = 0; dt < 8; dt++) {
                uint32_t vf[2];
                uint32_t voff = (uint32_t)(((t * 16 + (lane & 15)) * RS2 + dt * 8) * 2);
                ldmx2t(vf, sbase + F_V * 2 + voff);
                mmaf16(O[dt], pf, vf);
            }
        }
    }

    // ---- epilogue: /l and /32 quirk, fp16 store ----
    float inv0 = 1.f / (l0 * 32.f), inv1 = 1.f / (l1 * 32.f);
    int r = lane >> 2, c2 = (lane & 3) * 2;
    int q = q0 + wid * 16 + r;
    #pragma unroll
    for (int dt = 0; dt < 8; dt++) {
        int col = h * 64 + dt * 8 + c2;
        size_t off0 = (size_t)(b * N_ + q) * D_ + col;
        size_t off1 = (size_t)(b * N_ + q + 8) * D_ + col;
        *(uint32_t*)(oh + off0) = pack_h2(O[dt][0] * inv0, O[dt][1] * inv0);
        *(uint32_t*)(oh + off1) = pack_h2(O[dt][2] * inv1, O[dt][3] * inv1);
    }
}

// ===================================================================
extern "C" void kernel_launch(void* const* d_in, const int* in_sizes, int n_in,
                              void* d_out, int out_size)
{
    const float* hidden = (const float*)d_in[0];
    const float* w      = (const float*)d_in[1];
    const float* ln_g   = (const float*)d_in[2];
    const float* ln_b   = (const float*)d_in[3];
    const float* Wg     = (const float*)d_in[4];
    const float* bg     = (const float*)d_in[5];
    const float* Wb     = (const float*)d_in[6];
    const float* bb     = (const float*)d_in[7];
    const float* Wqkv   = (const float*)d_in[8];
    const float* bqkv   = (const float*)d_in[9];
    const float* Wp     = (const float*)d_in[10];
    const float* bp     = (const float*)d_in[11];
    float* out = (float*)d_out;

    float *p_qkv, *p_h1, *p_bqkv;
    __half *p_ah, *p_bh;
    cudaGetSymbolAddress((void**)&p_qkv, g_qkv);
    cudaGetSymbolAddress((void**)&p_h1, g_h1);
    cudaGetSymbolAddress((void**)&p_bqkv, g_bqkv);
    cudaGetSymbolAddress((void**)&p_ah, g_Ah);
    cudaGetSymbolAddress((void**)&p_bh, g_Bh);

    cudaFuncSetAttribute(flash_tc,
                         cudaFuncAttributeMaxDynamicSharedMemorySize, FLASH_SMEM);
    cudaFuncSetAttribute(gemm_mma,
                         cudaFuncAttributeMaxDynamicSharedMemorySize, GEMM_SMEM);

    // 1) gamma/beta + permuted qkv bias
    gamma_beta_kernel<<<32, 256>>>(w, Wg, bg, Wb, bb);
    permute_bias<<<12, 256>>>(bqkv);

    // 2) h = sln(hidden) -> fp16
    sln_kernel<<<M_, 256>>>(hidden, ln_g, ln_b, nullptr, p_ah, 0);

    // 3) qkv = h @ Wqkv^T + bqkv (permuted cols)
    cvt_half_permW<<<(QKV_ * D_) / 2048, 256>>>(Wqkv, p_bh);
    gemm_mma<<<dim3(QKV_ / 128, M_ / 128), 256, GEMM_SMEM>>>(
        p_ah, p_bh, p_bqkv, nullptr, p_qkv, M_, QKV_, D_);

    // 4) attention -> fp16 attn output in g_Ah
    flash_tc<<<dim3(N_ / 128, B_ * H_), 256, FLASH_SMEM>>>(p_ah);

    // 5) h1 = attn @ Wp^T + bp + hidden
    cvt_half<<<(D_ * D_) / 2048, 256>>>(Wp, p_bh);
    gemm_mma<<<dim3(D_ / 128, M_ / 128), 256, GEMM_SMEM>>>(
        p_ah, p_bh, bp, hidden, p_h1, M_, D_, D_);

    // 6) out = sln(h1) + h1
    sln_kernel<<<M_, 256>>>(p_h1, ln_g, ln_b, out, nullptr, 1);
}

// round 12
// speedup vs baseline: 5.0431x; 1.0069x over previous
#include <cuda_runtime.h>
#include <cuda_fp16.h>
#include <math.h>
#include <stdint.h>

// Shapes (fixed)
#define B_ 4
#define N_ 1024
#define D_ 1024
#define H_ 16
#define HD_ 64
#define M_ (B_ * N_)
#define QKV_ (3 * D_)

// -------- scratch --------
__device__ __half g_qkvh[M_ * QKV_];  // qkv fp16, layout [b,n][wh*1024+h*64+d]
__device__ float g_h1[M_ * D_];
__device__ float g_gamma[B_ * D_];
__device__ float g_beta[B_ * D_];
__device__ float g_bqkv[QKV_];
__device__ __half g_Ah[M_ * D_];      // fp16 activations
__device__ __half g_Bh[QKV_ * D_];    // fp16 weights

__device__ __forceinline__ uint32_t smem_to_u32(const void* p) {
    uint32_t a;
    asm("{ .reg .u64 t; cvta.to.shared.u64 t, %1; cvt.u32.u64 %0, t; }"
        : "=r"(a) : "l"(p));
    return a;
}
__device__ __forceinline__ uint32_t pack_h2(float a, float b) {
    __half2 h = __floats2half2_rn(a, b);
    return *(uint32_t*)&h;
}

// ===================================================================
// gamma/beta
// ===================================================================
__global__ __launch_bounds__(256) void gamma_beta_kernel(
    const float* __restrict__ w,
    const float* __restrict__ Wg, const float* __restrict__ bg,
    const float* __restrict__ Wb, const float* __restrict__ bb)
{
    int idx = blockIdx.x * 256 + threadIdx.x;
    int which = idx >> 12;
    int b = (idx >> 10) & 3;
    int d = idx & 1023;
    const float* Wrow = (which ? Wb : Wg) + (size_t)d * D_;
    const float* wr = w + b * D_;
    float acc = 0.f;
    #pragma unroll 4
    for (int k = 0; k < D_; k += 4) {
        float4 a = *(const float4*)&wr[k];
        float4 c = *(const float4*)&Wrow[k];
        acc += a.x * c.x + a.y * c.y + a.z * c.z + a.w * c.w;
    }
    if (which) g_beta[b * D_ + d]  = acc + bb[d];
    else       g_gamma[b * D_ + d] = acc + bg[d];
}

// ===================================================================
// SLN. oh==null: write fp32 (+res). else write fp16.
// ===================================================================
__global__ __launch_bounds__(256) void sln_kernel(
    const float* __restrict__ x,
    const float* __restrict__ ln_g, const float* __restrict__ ln_b,
    float* __restrict__ outf, __half* __restrict__ oh, int add_res)
{
    int row = blockIdx.x;
    int b = row >> 10;
    const float* xr = x + (size_t)row * D_;
    int t = threadIdx.x;

    float4 v = ((const float4*)xr)[t];
    float s  = v.x + v.y + v.z + v.w;
    float sq = v.x * v.x + v.y * v.y + v.z * v.z + v.w * v.w;
    #pragma unroll
    for (int o = 16; o; o >>= 1) {
        s  += __shfl_xor_sync(0xffffffffu, s, o);
        sq += __shfl_xor_sync(0xffffffffu, sq, o);
    }
    __shared__ float ss[8], ssq[8];
    int w = t >> 5, ln = t & 31;
    if (ln == 0) { ss[w] = s; ssq[w] = sq; }
    __syncthreads();
    s = 0.f; sq = 0.f;
    #pragma unroll
    for (int i = 0; i < 8; i++) { s += ss[i]; sq += ssq[i]; }

    float mu = s * (1.f / D_);
    float var = sq * (1.f / D_) - mu * mu;
    float rstd = rsqrtf(var + 1e-5f);

    float4 lg = ((const float4*)ln_g)[t];
    float4 lb = ((const float4*)ln_b)[t];
    float4 ga = ((const float4*)(g_gamma + b * D_))[t];
    float4 be = ((const float4*)(g_beta  + b * D_))[t];

    float4 r;
    r.x = ga.x * ((v.x - mu) * rstd * lg.x + lb.x) + be.x;
    r.y = ga.y * ((v.y - mu) * rstd * lg.y + lb.y) + be.y;
    r.z = ga.z * ((v.z - mu) * rstd * lg.z + lb.z) + be.z;
    r.w = ga.w * ((v.w - mu) * rstd * lg.w + lb.w) + be.w;
    if (add_res) { r.x += v.x; r.y += v.y; r.z += v.z; r.w += v.w; }
    if (outf) {
        ((float4*)(outf + (size_t)row * D_))[t] = r;
    } else {
        uint2 vh;
        vh.x = pack_h2(r.x, r.y);
        vh.y = pack_h2(r.z, r.w);
        *(uint2*)(oh + (size_t)row * D_ + t * 4) = vh;
    }
}

// ===================================================================
// cvt to fp16 (plain, for Wp)
// ===================================================================
__global__ __launch_bounds__(256) void cvt_half(
    const float* __restrict__ src, __half* __restrict__ dst)
{
    int i = (blockIdx.x * 256 + threadIdx.x) * 8;
    float4 a = *(const float4*)(src + i);
    float4 b = *(const float4*)(src + i + 4);
    uint4 vh;
    vh.x = pack_h2(a.x, a.y);
    vh.y = pack_h2(a.z, a.w);
    vh.z = pack_h2(b.x, b.y);
    vh.w = pack_h2(b.z, b.w);
    *(uint4*)(dst + i) = vh;
}

// ===================================================================
// cvt fp16 with qkv row permutation: h*192+d*3+wh -> wh*1024+h*64+d
// ===================================================================
__global__ __launch_bounds__(256) void cvt_half_permW(
    const float* __restrict__ src, __half* __restrict__ dst)
{
    int idx = (blockIdx.x * 256 + threadIdx.x) * 8;
    int row = idx >> 10, col = idx & 1023;
    int h = row / 192, rem = row % 192;
    int d = rem / 3, wh = rem % 3;
    size_t dsti = ((size_t)(wh * 1024 + h * 64 + d) << 10) + col;
    float4 a = *(const float4*)(src + idx);
    float4 b = *(const float4*)(src + idx + 4);
    uint4 vh;
    vh.x = pack_h2(a.x, a.y);
    vh.y = pack_h2(a.z, a.w);
    vh.z = pack_h2(b.x, b.y);
    vh.w = pack_h2(b.z, b.w);
    *(uint4*)(dst + dsti) = vh;
}

__global__ void permute_bias(const float* __restrict__ b) {
    int r = blockIdx.x * 256 + threadIdx.x;
    if (r < QKV_) {
        int h = r / 192, rem = r % 192;
        int d = rem / 3, wh = rem % 3;
        g_bqkv[wh * 1024 + h * 64 + d] = b[r];
    }
}

// ===================================================================
// mma helpers (fp16)
// ===================================================================
__device__ __forceinline__ void ldmx4(uint32_t* r, uint32_t addr) {
    asm volatile("ldmatrix.sync.aligned.m8n8.x4.shared.b16 {%0,%1,%2,%3}, [%4];"
                 : "=r"(r[0]), "=r"(r[1]), "=r"(r[2]), "=r"(r[3]) : "r"(addr));
}
__device__ __forceinline__ void ldmx2(uint32_t* r, uint32_t addr) {
    asm volatile("ldmatrix.sync.aligned.m8n8.x2.shared.b16 {%0,%1}, [%2];"
                 : "=r"(r[0]), "=r"(r[1]) : "r"(addr));
}
__device__ __forceinline__ void ldmx2t(uint32_t* r, uint32_t addr) {
    asm volatile("ldmatrix.sync.aligned.m8n8.x2.trans.shared.b16 {%0,%1}, [%2];"
                 : "=r"(r[0]), "=r"(r[1]) : "r"(addr));
}
__device__ __forceinline__ void mmaf16(float* c, const uint32_t* a, const uint32_t* b) {
    asm volatile("mma.sync.aligned.m16n8k16.row.col.f32.f16.f16.f32 "
                 "{%0,%1,%2,%3}, {%4,%5,%6,%7}, {%8,%9}, {%0,%1,%2,%3};"
                 : "+f"(c[0]), "+f"(c[1]), "+f"(c[2]), "+f"(c[3])
                 : "r"(a[0]), "r"(a[1]), "r"(a[2]), "r"(a[3]), "r"(b[0]), "r"(b[1]));
}

// ===================================================================
// fp16 GEMM: out = A @ W^T + bias (+residual). CTA 128x128, BK=64,
// 3-stage cp.async, 8 warps (2x4), 2 CTAs/SM.
// Ch != null -> fp16 output; else fp32 C (+residual).
// ===================================================================
#define RSG 72
#define MAT_ELEMS (128 * RSG)           // 9216
#define STAGE_ELEMS (2 * MAT_ELEMS)     // 18432
#define GEMM_SMEM (3 * STAGE_ELEMS * 2) // 110592 B -> 2 CTAs/SM

__global__ __launch_bounds__(256, 2) void gemm_mma(
    const __half* __restrict__ A, const __half* __restrict__ Wt,
    const float* __restrict__ bias, const float* __restrict__ residual,
    float* __restrict__ C, __half* __restrict__ Ch, int M, int N, int K)
{
    extern __shared__ __half smh[];
    uint32_t sbase = smem_to_u32(smh);
    int tid = threadIdx.x, wid = tid >> 5, lane = tid & 31;
    int m0 = blockIdx.y * 128, n0 = blockIdx.x * 128;
    int wm = wid >> 2, wn = wid & 3;

    float acc[4][4][4];
    #pragma unroll
    for (int i = 0; i < 4; i++)
        #pragma unroll
        for (int j = 0; j < 4; j++)
            #pragma unroll
            for (int c = 0; c < 4; c++) acc[i][j][c] = 0.f;

    const int nch = K >> 6;   // BK=64

    auto load_stage = [&](int ch, int s) {
        int kk = ch << 6;
        #pragma unroll
        for (int t = 0; t < 8; t++) {
            int idx = t * 256 + tid;        // 0..2047
            int mat = idx >> 10;            // 0..1
            int row = (idx >> 3) & 127;
            int seg = idx & 7;
            const __half* src = mat ? Wt : A;
            int rb = mat ? n0 : m0;
            const __half* g = src + (size_t)(rb + row) * K + kk + seg * 8;
            uint32_t dst = sbase + (uint32_t)((s * STAGE_ELEMS + mat * MAT_ELEMS
                                               + row * RSG + seg * 8) * 2);
            asm volatile("cp.async.cg.shared.global [%0], [%1], 16;"
                         :: "r"(dst), "l"(g) : "memory");
        }
        asm volatile("cp.async.commit_group;" ::: "memory");
    };

    auto compute_stage = [&](int s) {
        uint32_t stage_b = sbase + (uint32_t)(s * STAGE_ELEMS * 2);
        #pragma unroll
        for (int ks = 0; ks < 4; ks++) {
            uint32_t af[4][4];
            int arow = wm * 64 + (lane & 15);
            int acol = ks * 16 + (lane >> 4) * 8;
            #pragma unroll
            for (int i = 0; i < 4; i++) {
                uint32_t off = (uint32_t)(((arow + i * 16) * RSG + acol) * 2);
                ldmx4(af[i], stage_b + off);
            }
            uint32_t bf[4][2];
            int bl = lane & 15;
            int brow = wn * 32 + (bl & 7);
            int bcol = ks * 16 + (bl >> 3) * 8;
            #pragma unroll
            for (int j = 0; j < 4; j++) {
                uint32_t off = (uint32_t)(((brow + j * 8) * RSG + bcol) * 2);
                ldmx2(bf[j], stage_b + MAT_ELEMS * 2 + off);
            }
            #pragma unroll
            for (int i = 0; i < 4; i++)
                #pragma unroll
                for (int j = 0; j < 4; j++)
                    mmaf16(acc[i][j], af[i], bf[j]);
        }
    };

    load_stage(0, 0);
    load_stage(1, 1);
    for (int ch = 0; ch < nch; ch++) {
        if (ch + 2 < nch) {
            load_stage(ch + 2, (ch + 2) % 3);
            asm volatile("cp.async.wait_group 2;" ::: "memory");
        } else if (ch + 1 < nch) {
            asm volatile("cp.async.wait_group 1;" ::: "memory");
        } else {
            asm volatile("cp.async.wait_group 0;" ::: "memory");
        }
        __syncthreads();
        compute_stage(ch % 3);
        __syncthreads();
    }

    int r = lane >> 2, cp2 = (lane & 3) * 2;
    #pragma unroll
    for (int i = 0; i < 4; i++) {
        int row0 = m0 + wm * 64 + i * 16 + r;
        #pragma unroll
        for (int j = 0; j < 4; j++) {
            int col = n0 + wn * 32 + j * 8 + cp2;
            float2 bv = *(const float2*)(bias + col);
            float2 o0, o1;
            o0.x = acc[i][j][0] + bv.x; o0.y = acc[i][j][1] + bv.y;
            o1.x = acc[i][j][2] + bv.x; o1.y = acc[i][j][3] + bv.y;
            if (Ch) {
                *(uint32_t*)(Ch + (size_t)row0 * N + col) = pack_h2(o0.x, o0.y);
                *(uint32_t*)(Ch + (size_t)(row0 + 8) * N + col) = pack_h2(o1.x, o1.y);
            } else {
                if (residual) {
                    float2 r0 = *(const float2*)(residual + (size_t)row0 * N + col);
                    float2 r1 = *(const float2*)(residual + (size_t)(row0 + 8) * N + col);
                    o0.x += r0.x; o0.y += r0.y;
                    o1.x += r1.x; o1.y += r1.y;
                }
                *(float2*)(C + (size_t)row0 * N + col) = o0;
                *(float2*)(C + (size_t)(row0 + 8) * N + col) = o1;
            }
        }
    }
}

// ===================================================================
// fp16 flash attention over fp16 qkv buffer (straight uint4 copies to
// smem). Q tile 128, key blk 64, 8 warps x 16 q-rows. fp32 softmax.
// ===================================================================
#define RS2 72
#define F_Q 0
#define F_K (128 * RS2)
#define F_V (F_K + 64 * RS2)
#define FLASH_SMEM ((F_V + 64 * RS2) * 2)   // 36864 B

__global__ __launch_bounds__(256, 2) void flash_tc(__half* __restrict__ oh)
{
    extern __shared__ __half smh[];
    uint32_t sbase = smem_to_u32(smh);
    int tid = threadIdx.x, wid = tid >> 5, lane = tid & 31;
    int bh = blockIdx.y;
    int b = bh >> 4, h = bh & 15;
    int q0 = blockIdx.x * 128;
    const __half* qkvh = g_qkvh;
    size_t rowbase = (size_t)(b * N_) * QKV_ + h * 64;

    // Q tile 128x64: 1024 16B-chunks
    #pragma unroll
    for (int it = 0; it < 4; it++) {
        int i = it * 256 + tid;
        int q = i >> 3, dg = (i & 7) * 8;
        uint4 v = *(const uint4*)(qkvh + rowbase + (size_t)(q0 + q) * QKV_ + dg);
        *(uint4*)(smh + F_Q + q * RS2 + dg) = v;
    }

    float mr0 = -1e30f, mr1 = -1e30f, l0 = 0.f, l1 = 0.f;
    float O[8][4] = {};

    for (int kb = 0; kb < N_; kb += 64) {
        __syncthreads();
        // K+V: 2 x 64 rows x 8 chunks = 1024 chunks
        #pragma unroll
        for (int it = 0; it < 4; it++) {
            int i = it * 256 + tid;
            int mat = i >> 9;               // 0=K, 1=V
            int r = (i >> 3) & 63;
            int dg = (i & 7) * 8;
            size_t p = rowbase + (size_t)(kb + r) * QKV_ + (mat ? 2048 : 1024) + dg;
            uint4 v = *(const uint4*)(qkvh + p);
            *(uint4*)(smh + (mat ? F_V : F_K) + r * RS2 + dg) = v;
        }
        __syncthreads();

        // ---- S = Q K^T ----
        float S[8][4];
        #pragma unroll
        for (int j = 0; j < 8; j++)
            #pragma unroll
            for (int c = 0; c < 4; c++) S[j][c] = 0.f;

        #pragma unroll
        for (int ks = 0; ks < 4; ks++) {
            uint32_t qf[4];
            uint32_t aoff = (uint32_t)(((wid * 16 + (lane & 15)) * RS2
                                        + ks * 16 + (lane >> 4) * 8) * 2);
            ldmx4(qf, sbase + F_Q * 2 + aoff);
            #pragma unroll
            for (int j = 0; j < 8; j++) {
                uint32_t kf[2];
                uint32_t boff = (uint32_t)(((j * 8 + (lane & 7)) * RS2
                                            + ks * 16 + ((lane & 15) >> 3) * 8) * 2);
                ldmx2(kf, sbase + F_K * 2 + boff);
                mmaf16(S[j], qf, kf);
            }
        }

        // ---- online softmax ----
        float rm0 = -1e30f, rm1 = -1e30f;
        #pragma unroll
        for (int j = 0; j < 8; j++) {
            rm0 = fmaxf(rm0, fmaxf(S[j][0], S[j][1]));
            rm1 = fmaxf(rm1, fmaxf(S[j][2], S[j][3]));
        }
        rm0 = fmaxf(rm0, __shfl_xor_sync(0xffffffffu, rm0, 1));
        rm0 = fmaxf(rm0, __shfl_xor_sync(0xffffffffu, rm0, 2));
        rm1 = fmaxf(rm1, __shfl_xor_sync(0xffffffffu, rm1, 1));
        rm1 = fmaxf(rm1, __shfl_xor_sync(0xffffffffu, rm1, 2));
        float mn0 = fmaxf(mr0, rm0), mn1 = fmaxf(mr1, rm1);
        float sc0 = __expf(mr0 - mn0), sc1 = __expf(mr1 - mn1);
        float rs0 = 0.f, rs1 = 0.f;
        #pragma unroll
        for (int j = 0; j < 8; j++) {
            S[j][0] = __expf(S[j][0] - mn0);
            S[j][1] = __expf(S[j][1] - mn0);
            S[j][2] = __expf(S[j][2] - mn1);
            S[j][3] = __expf(S[j][3] - mn1);
            rs0 += S[j][0] + S[j][1];
            rs1 += S[j][2] + S[j][3];
        }
        rs0 += __shfl_xor_sync(0xffffffffu, rs0, 1);
        rs0 += __shfl_xor_sync(0xffffffffu, rs0, 2);
        rs1 += __shfl_xor_sync(0xffffffffu, rs1, 1);
        rs1 += __shfl_xor_sync(0xffffffffu, rs1, 2);
        l0 = l0 * sc0 + rs0;
        l1 = l1 * sc1 + rs1;
        mr0 = mn0; mr1 = mn1;
        #pragma unroll
        for (int j = 0; j < 8; j++) {
            O[j][0] *= sc0; O[j][1] *= sc0;
            O[j][2] *= sc1; O[j][3] *= sc1;
        }

        // ---- O += P V ----
        #pragma unroll
        for (int t = 0; t < 4; t++) {
            uint32_t pf[4];
            pf[0] = pack_h2(S[2 * t][0],     S[2 * t][1]);
            pf[1] = pack_h2(S[2 * t][2],     S[2 * t][3]);
            pf[2] = pack_h2(S[2 * t + 1][0], S[2 * t + 1][1]);
            pf[3] = pack_h2(S[2 * t + 1][2], S[2 * t + 1][3]);
            #pragma unroll
            for (int dt = 0; dt < 8; dt++) {
                uint32_t vf[2];
                uint32_t voff = (uint32_t)(((t * 16 + (lane & 15)) * RS2 + dt * 8) * 2);
                ldmx2t(vf, sbase + F_V * 2 + voff);
                mmaf16(O[dt], pf, vf);
            }
        }
    }

    // ---- epilogue: /l and /32 quirk, fp16 store ----
    float inv0 = 1.f / (l0 * 32.f), inv1 = 1.f / (l1 * 32.f);
    int r = lane >> 2, c2 = (lane & 3) * 2;
    int q = q0 + wid * 16 + r;
    #pragma unroll
    for (int dt = 0; dt < 8; dt++) {
        int col = h * 64 + dt * 8 + c2;
        size_t off0 = (size_t)(b * N_ + q) * D_ + col;
        size_t off1 = (size_t)(b * N_ + q + 8) * D_ + col;
        *(uint32_t*)(oh + off0) = pack_h2(O[dt][0] * inv0, O[dt][1] * inv0);
        *(uint32_t*)(oh + off1) = pack_h2(O[dt][2] * inv1, O[dt][3] * inv1);
    }
}

// ===================================================================
extern "C" void kernel_launch(void* const* d_in, const int* in_sizes, int n_in,
                              void* d_out, int out_size)
{
    const float* hidden = (const float*)d_in[0];
    const float* w      = (const float*)d_in[1];
    const float* ln_g   = (const float*)d_in[2];
    const float* ln_b   = (const float*)d_in[3];
    const float* Wg     = (const float*)d_in[4];
    const float* bg     = (const float*)d_in[5];
    const float* Wb     = (const float*)d_in[6];
    const float* bb     = (const float*)d_in[7];
    const float* Wqkv   = (const float*)d_in[8];
    const float* bqkv   = (const float*)d_in[9];
    const float* Wp     = (const float*)d_in[10];
    const float* bp     = (const float*)d_in[11];
    float* out = (float*)d_out;

    float *p_h1, *p_bqkv;
    __half *p_qkvh, *p_ah, *p_bh;
    cudaGetSymbolAddress((void**)&p_qkvh, g_qkvh);
    cudaGetSymbolAddress((void**)&p_h1, g_h1);
    cudaGetSymbolAddress((void**)&p_bqkv, g_bqkv);
    cudaGetSymbolAddress((void**)&p_ah, g_Ah);
    cudaGetSymbolAddress((void**)&p_bh, g_Bh);

    cudaFuncSetAttribute(flash_tc,
                         cudaFuncAttributeMaxDynamicSharedMemorySize, FLASH_SMEM);
    cudaFuncSetAttribute(gemm_mma,
                         cudaFuncAttributeMaxDynamicSharedMemorySize, GEMM_SMEM);

    // 1) gamma/beta + permuted qkv bias
    gamma_beta_kernel<<<32, 256>>>(w, Wg, bg, Wb, bb);
    permute_bias<<<12, 256>>>(bqkv);

    // 2) h = sln(hidden) -> fp16
    sln_kernel<<<M_, 256>>>(hidden, ln_g, ln_b, nullptr, p_ah, 0);

    // 3) qkv = h @ Wqkv^T + bqkv (permuted cols) -> fp16
    cvt_half_permW<<<(QKV_ * D_) / 2048, 256>>>(Wqkv, p_bh);
    gemm_mma<<<dim3(QKV_ / 128, M_ / 128), 256, GEMM_SMEM>>>(
        p_ah, p_bh, p_bqkv, nullptr, nullptr, p_qkvh, M_, QKV_, D_);

    // 4) attention -> fp16 attn output in g_Ah
    flash_tc<<<dim3(N_ / 128, B_ * H_), 256, FLASH_SMEM>>>(p_ah);

    // 5) h1 = attn @ Wp^T + bp + hidden (fp32 out)
    cvt_half<<<(D_ * D_) / 2048, 256>>>(Wp, p_bh);
    gemm_mma<<<dim3(D_ / 128, M_ / 128), 256, GEMM_SMEM>>>(
        p_ah, p_bh, bp, hidden, p_h1, nullptr, M_, D_, D_);

    // 6) out = sln(h1) + h1
    sln_kernel<<<M_, 256>>>(p_h1, ln_g, ln_b, out, nullptr, 1);
}

// round 13
// speedup vs baseline: 5.1921x; 1.0295x over previous
#include <cuda_runtime.h>
#include <cuda_fp16.h>
#include <math.h>
#include <stdint.h>

// Shapes (fixed)
#define B_ 4
#define N_ 1024
#define D_ 1024
#define H_ 16
#define HD_ 64
#define M_ (B_ * N_)
#define QKV_ (3 * D_)
#define L2E 1.4426950408889634f

// -------- scratch --------
__device__ __half g_qkvh[M_ * QKV_];  // qkv fp16, layout [b,n][wh*1024+h*64+d]
__device__ float g_h1[M_ * D_];
__device__ float g_gamma[B_ * D_];
__device__ float g_beta[B_ * D_];
__device__ float g_bqkv[QKV_];
__device__ __half g_Ah[M_ * D_];      // fp16 activations
__device__ __half g_Bh[QKV_ * D_];    // fp16 weights

__device__ __forceinline__ uint32_t smem_to_u32(const void* p) {
    uint32_t a;
    asm("{ .reg .u64 t; cvta.to.shared.u64 t, %1; cvt.u32.u64 %0, t; }"
        : "=r"(a) : "l"(p));
    return a;
}
__device__ __forceinline__ uint32_t pack_h2(float a, float b) {
    __half2 h = __floats2half2_rn(a, b);
    return *(uint32_t*)&h;
}
// exp2 of two fp32 values -> packed fp16x2 (one MUFU op for 2 elements)
__device__ __forceinline__ uint32_t exp2_h2(float x0, float x1) {
    uint32_t p = pack_h2(x0, x1);
    uint32_t r;
    asm("ex2.approx.f16x2 %0, %1;" : "=r"(r) : "r"(p));
    return r;
}

// ===================================================================
// gamma/beta
// ===================================================================
__global__ __launch_bounds__(256) void gamma_beta_kernel(
    const float* __restrict__ w,
    const float* __restrict__ Wg, const float* __restrict__ bg,
    const float* __restrict__ Wb, const float* __restrict__ bb)
{
    int idx = blockIdx.x * 256 + threadIdx.x;
    int which = idx >> 12;
    int b = (idx >> 10) & 3;
    int d = idx & 1023;
    const float* Wrow = (which ? Wb : Wg) + (size_t)d * D_;
    const float* wr = w + b * D_;
    float acc = 0.f;
    #pragma unroll 4
    for (int k = 0; k < D_; k += 4) {
        float4 a = *(const float4*)&wr[k];
        float4 c = *(const float4*)&Wrow[k];
        acc += a.x * c.x + a.y * c.y + a.z * c.z + a.w * c.w;
    }
    if (which) g_beta[b * D_ + d]  = acc + bb[d];
    else       g_gamma[b * D_ + d] = acc + bg[d];
}

// ===================================================================
// SLN. oh==null: write fp32 (+res). else write fp16.
// ===================================================================
__global__ __launch_bounds__(256) void sln_kernel(
    const float* __restrict__ x,
    const float* __restrict__ ln_g, const float* __restrict__ ln_b,
    float* __restrict__ outf, __half* __restrict__ oh, int add_res)
{
    int row = blockIdx.x;
    int b = row >> 10;
    const float* xr = x + (size_t)row * D_;
    int t = threadIdx.x;

    float4 v = ((const float4*)xr)[t];
    float s  = v.x + v.y + v.z + v.w;
    float sq = v.x * v.x + v.y * v.y + v.z * v.z + v.w * v.w;
    #pragma unroll
    for (int o = 16; o; o >>= 1) {
        s  += __shfl_xor_sync(0xffffffffu, s, o);
        sq += __shfl_xor_sync(0xffffffffu, sq, o);
    }
    __shared__ float ss[8], ssq[8];
    int w = t >> 5, ln = t & 31;
    if (ln == 0) { ss[w] = s; ssq[w] = sq; }
    __syncthreads();
    s = 0.f; sq = 0.f;
    #pragma unroll
    for (int i = 0; i < 8; i++) { s += ss[i]; sq += ssq[i]; }

    float mu = s * (1.f / D_);
    float var = sq * (1.f / D_) - mu * mu;
    float rstd = rsqrtf(var + 1e-5f);

    float4 lg = ((const float4*)ln_g)[t];
    float4 lb = ((const float4*)ln_b)[t];
    float4 ga = ((const float4*)(g_gamma + b * D_))[t];
    float4 be = ((const float4*)(g_beta  + b * D_))[t];

    float4 r;
    r.x = ga.x * ((v.x - mu) * rstd * lg.x + lb.x) + be.x;
    r.y = ga.y * ((v.y - mu) * rstd * lg.y + lb.y) + be.y;
    r.z = ga.z * ((v.z - mu) * rstd * lg.z + lb.z) + be.z;
    r.w = ga.w * ((v.w - mu) * rstd * lg.w + lb.w) + be.w;
    if (add_res) { r.x += v.x; r.y += v.y; r.z += v.z; r.w += v.w; }
    if (outf) {
        ((float4*)(outf + (size_t)row * D_))[t] = r;
    } else {
        uint2 vh;
        vh.x = pack_h2(r.x, r.y);
        vh.y = pack_h2(r.z, r.w);
        *(uint2*)(oh + (size_t)row * D_ + t * 4) = vh;
    }
}

// ===================================================================
// cvt to fp16 (plain, for Wp)
// ===================================================================
__global__ __launch_bounds__(256) void cvt_half(
    const float* __restrict__ src, __half* __restrict__ dst)
{
    int i = (blockIdx.x * 256 + threadIdx.x) * 8;
    float4 a = *(const float4*)(src + i);
    float4 b = *(const float4*)(src + i + 4);
    uint4 vh;
    vh.x = pack_h2(a.x, a.y);
    vh.y = pack_h2(a.z, a.w);
    vh.z = pack_h2(b.x, b.y);
    vh.w = pack_h2(b.z, b.w);
    *(uint4*)(dst + i) = vh;
}

// ===================================================================
// cvt fp16 with qkv row permutation: h*192+d*3+wh -> wh*1024+h*64+d
// ===================================================================
__global__ __launch_bounds__(256) void cvt_half_permW(
    const float* __restrict__ src, __half* __restrict__ dst)
{
    int idx = (blockIdx.x * 256 + threadIdx.x) * 8;
    int row = idx >> 10, col = idx & 1023;
    int h = row / 192, rem = row % 192;
    int d = rem / 3, wh = rem % 3;
    size_t dsti = ((size_t)(wh * 1024 + h * 64 + d) << 10) + col;
    float4 a = *(const float4*)(src + idx);
    float4 b = *(const float4*)(src + idx + 4);
    uint4 vh;
    vh.x = pack_h2(a.x, a.y);
    vh.y = pack_h2(a.z, a.w);
    vh.z = pack_h2(b.x, b.y);
    vh.w = pack_h2(b.z, b.w);
    *(uint4*)(dst + dsti) = vh;
}

__global__ void permute_bias(const float* __restrict__ b) {
    int r = blockIdx.x * 256 + threadIdx.x;
    if (r < QKV_) {
        int h = r / 192, rem = r % 192;
        int d = rem / 3, wh = rem % 3;
        g_bqkv[wh * 1024 + h * 64 + d] = b[r];
    }
}

// ===================================================================
// mma helpers (fp16)
// ===================================================================
__device__ __forceinline__ void ldmx4(uint32_t* r, uint32_t addr) {
    asm volatile("ldmatrix.sync.aligned.m8n8.x4.shared.b16 {%0,%1,%2,%3}, [%4];"
                 : "=r"(r[0]), "=r"(r[1]), "=r"(r[2]), "=r"(r[3]) : "r"(addr));
}
__device__ __forceinline__ void ldmx4t(uint32_t* r, uint32_t addr) {
    asm volatile("ldmatrix.sync.aligned.m8n8.x4.trans.shared.b16 {%0,%1,%2,%3}, [%4];"
                 : "=r"(r[0]), "=r"(r[1]), "=r"(r[2]), "=r"(r[3]) : "r"(addr));
}
__device__ __forceinline__ void mmaf16(float* c, const uint32_t* a, const uint32_t* b) {
    asm volatile("mma.sync.aligned.m16n8k16.row.col.f32.f16.f16.f32 "
                 "{%0,%1,%2,%3}, {%4,%5,%6,%7}, {%8,%9}, {%0,%1,%2,%3};"
                 : "+f"(c[0]), "+f"(c[1]), "+f"(c[2]), "+f"(c[3])
                 : "r"(a[0]), "r"(a[1]), "r"(a[2]), "r"(a[3]), "r"(b[0]), "r"(b[1]));
}

// ===================================================================
// fp16 GEMM: out = A @ W^T + bias (+residual). CTA 128x128, BK=64,
// 3-stage cp.async, 8 warps (2x4), 2 CTAs/SM. B frags via x4 pairs.
// ===================================================================
#define RSG 72
#define MAT_ELEMS (128 * RSG)           // 9216
#define STAGE_ELEMS (2 * MAT_ELEMS)     // 18432
#define GEMM_SMEM (3 * STAGE_ELEMS * 2) // 110592 B -> 2 CTAs/SM

__global__ __launch_bounds__(256, 2) void gemm_mma(
    const __half* __restrict__ A, const __half* __restrict__ Wt,
    const float* __restrict__ bias, const float* __restrict__ residual,
    float* __restrict__ C, __half* __restrict__ Ch, int M, int N, int K)
{
    extern __shared__ __half smh[];
    uint32_t sbase = smem_to_u32(smh);
    int tid = threadIdx.x, wid = tid >> 5, lane = tid & 31;
    int m0 = blockIdx.y * 128, n0 = blockIdx.x * 128;
    int wm = wid >> 2, wn = wid & 3;
    int g8 = lane >> 3;                 // lane octet 0..3

    float acc[4][4][4];
    #pragma unroll
    for (int i = 0; i < 4; i++)
        #pragma unroll
        for (int j = 0; j < 4; j++)
            #pragma unroll
            for (int c = 0; c < 4; c++) acc[i][j][c] = 0.f;

    const int nch = K >> 6;   // BK=64

    auto load_stage = [&](int ch, int s) {
        int kk = ch << 6;
        #pragma unroll
        for (int t = 0; t < 8; t++) {
            int idx = t * 256 + tid;
            int mat = idx >> 10;
            int row = (idx >> 3) & 127;
            int seg = idx & 7;
            const __half* src = mat ? Wt : A;
            int rb = mat ? n0 : m0;
            const __half* g = src + (size_t)(rb + row) * K + kk + seg * 8;
            uint32_t dst = sbase + (uint32_t)((s * STAGE_ELEMS + mat * MAT_ELEMS
                                               + row * RSG + seg * 8) * 2);
            asm volatile("cp.async.cg.shared.global [%0], [%1], 16;"
                         :: "r"(dst), "l"(g) : "memory");
        }
        asm volatile("cp.async.commit_group;" ::: "memory");
    };

    auto compute_stage = [&](int s) {
        uint32_t stage_b = sbase + (uint32_t)(s * STAGE_ELEMS * 2);
        #pragma unroll
        for (int ks = 0; ks < 4; ks++) {
            uint32_t af[4][4];
            int arow = wm * 64 + (lane & 15);
            int acol = ks * 16 + (lane >> 4) * 8;
            #pragma unroll
            for (int i = 0; i < 4; i++) {
                uint32_t off = (uint32_t)(((arow + i * 16) * RSG + acol) * 2);
                ldmx4(af[i], stage_b + off);
            }
            // B fragments: x4 serves two n-tiles per instruction
            uint32_t bq[2][4];
            #pragma unroll
            for (int jp = 0; jp < 2; jp++) {
                int brow = wn * 32 + jp * 16 + (g8 >> 1) * 8 + (lane & 7);
                int bcol = ks * 16 + (g8 & 1) * 8;
                uint32_t off = (uint32_t)((brow * RSG + bcol) * 2);
                ldmx4(bq[jp], stage_b + MAT_ELEMS * 2 + off);
            }
            #pragma unroll
            for (int i = 0; i < 4; i++)
                #pragma unroll
                for (int j = 0; j < 4; j++)
                    mmaf16(acc[i][j], af[i], &bq[j >> 1][(j & 1) * 2]);
        }
    };

    load_stage(0, 0);
    load_stage(1, 1);
    for (int ch = 0; ch < nch; ch++) {
        if (ch + 2 < nch) {
            load_stage(ch + 2, (ch + 2) % 3);
            asm volatile("cp.async.wait_group 2;" ::: "memory");
        } else if (ch + 1 < nch) {
            asm volatile("cp.async.wait_group 1;" ::: "memory");
        } else {
            asm volatile("cp.async.wait_group 0;" ::: "memory");
        }
        __syncthreads();
        compute_stage(ch % 3);
        __syncthreads();
    }

    int r = lane >> 2, cp2 = (lane & 3) * 2;
    #pragma unroll
    for (int i = 0; i < 4; i++) {
        int row0 = m0 + wm * 64 + i * 16 + r;
        #pragma unroll
        for (int j = 0; j < 4; j++) {
            int col = n0 + wn * 32 + j * 8 + cp2;
            float2 bv = *(const float2*)(bias + col);
            float2 o0, o1;
            o0.x = acc[i][j][0] + bv.x; o0.y = acc[i][j][1] + bv.y;
            o1.x = acc[i][j][2] + bv.x; o1.y = acc[i][j][3] + bv.y;
            if (Ch) {
                *(uint32_t*)(Ch + (size_t)row0 * N + col) = pack_h2(o0.x, o0.y);
                *(uint32_t*)(Ch + (size_t)(row0 + 8) * N + col) = pack_h2(o1.x, o1.y);
            } else {
                if (residual) {
                    float2 r0 = *(const float2*)(residual + (size_t)row0 * N + col);
                    float2 r1 = *(const float2*)(residual + (size_t)(row0 + 8) * N + col);
                    o0.x += r0.x; o0.y += r0.y;
                    o1.x += r1.x; o1.y += r1.y;
                }
                *(float2*)(C + (size_t)row0 * N + col) = o0;
                *(float2*)(C + (size_t)(row0 + 8) * N + col) = o1;
            }
        }
    }
}

// ===================================================================
// fp16 flash attention. Q tile 128, key blk 64, 8 warps x 16 q-rows.
// fp16x2 exp (ex2.approx.f16x2), x4-paired LDSM for K and V.
// ===================================================================
#define RS2 72
#define F_Q 0
#define F_K (128 * RS2)
#define F_V (F_K + 64 * RS2)
#define FLASH_SMEM ((F_V + 64 * RS2) * 2)   // 36864 B

__global__ __launch_bounds__(256, 2) void flash_tc(__half* __restrict__ oh)
{
    extern __shared__ __half smh[];
    uint32_t sbase = smem_to_u32(smh);
    int tid = threadIdx.x, wid = tid >> 5, lane = tid & 31;
    int g8 = lane >> 3;
    int bh = blockIdx.y;
    int b = bh >> 4, h = bh & 15;
    int q0 = blockIdx.x * 128;
    const __half* qkvh = g_qkvh;
    size_t rowbase = (size_t)(b * N_) * QKV_ + h * 64;

    // Q tile 128x64: 1024 16B-chunks
    #pragma unroll
    for (int it = 0; it < 4; it++) {
        int i = it * 256 + tid;
        int q = i >> 3, dg = (i & 7) * 8;
        uint4 v = *(const uint4*)(qkvh + rowbase + (size_t)(q0 + q) * QKV_ + dg);
        *(uint4*)(smh + F_Q + q * RS2 + dg) = v;
    }

    float mr0 = -1e30f, mr1 = -1e30f, l0 = 0.f, l1 = 0.f;
    float O[8][4] = {};

    for (int kb = 0; kb < N_; kb += 64) {
        __syncthreads();
        #pragma unroll
        for (int it = 0; it < 4; it++) {
            int i = it * 256 + tid;
            int mat = i >> 9;               // 0=K, 1=V
            int r = (i >> 3) & 63;
            int dg = (i & 7) * 8;
            size_t p = rowbase + (size_t)(kb + r) * QKV_ + (mat ? 2048 : 1024) + dg;
            uint4 v = *(const uint4*)(qkvh + p);
            *(uint4*)(smh + (mat ? F_V : F_K) + r * RS2 + dg) = v;
        }
        __syncthreads();

        // ---- S = Q K^T (K frags via x4 pairs) ----
        float S[8][4];
        #pragma unroll
        for (int j = 0; j < 8; j++)
            #pragma unroll
            for (int c = 0; c < 4; c++) S[j][c] = 0.f;

        #pragma unroll
        for (int ks = 0; ks < 4; ks++) {
            uint32_t qf[4];
            uint32_t aoff = (uint32_t)(((wid * 16 + (lane & 15)) * RS2
                                        + ks * 16 + (lane >> 4) * 8) * 2);
            ldmx4(qf, sbase + F_Q * 2 + aoff);
            #pragma unroll
            for (int j = 0; j < 8; j += 2) {
                uint32_t kf[4];
                int krow = j * 8 + (g8 >> 1) * 8 + (lane & 7);
                int kcol = ks * 16 + (g8 & 1) * 8;
                ldmx4(kf, sbase + F_K * 2 + (uint32_t)((krow * RS2 + kcol) * 2));
                mmaf16(S[j], qf, kf);
                mmaf16(S[j + 1], qf, kf + 2);
            }
        }

        // ---- online softmax (fp32 max, fp16x2 exp) ----
        float rm0 = -1e30f, rm1 = -1e30f;
        #pragma unroll
        for (int j = 0; j < 8; j++) {
            rm0 = fmaxf(rm0, fmaxf(S[j][0], S[j][1]));
            rm1 = fmaxf(rm1, fmaxf(S[j][2], S[j][3]));
        }
        rm0 = fmaxf(rm0, __shfl_xor_sync(0xffffffffu, rm0, 1));
        rm0 = fmaxf(rm0, __shfl_xor_sync(0xffffffffu, rm0, 2));
        rm1 = fmaxf(rm1, __shfl_xor_sync(0xffffffffu, rm1, 1));
        rm1 = fmaxf(rm1, __shfl_xor_sync(0xffffffffu, rm1, 2));
        float mn0 = fmaxf(mr0, rm0), mn1 = fmaxf(mr1, rm1);
        float sc0 = __expf(mr0 - mn0), sc1 = __expf(mr1 - mn1);
        #pragma unroll
        for (int j = 0; j < 8; j++) {
            O[j][0] *= sc0; O[j][1] *= sc0;
            O[j][2] *= sc1; O[j][3] *= sc1;
        }
        float nl0 = mn0 * L2E, nl1 = mn1 * L2E;
        __half2 hs0 = __floats2half2_rn(0.f, 0.f);
        __half2 hs1 = hs0;

        // ---- P = exp(S-mn) as fp16x2 frags; O += P V (V via x4t pairs) ----
        #pragma unroll
        for (int t = 0; t < 4; t++) {
            uint32_t pf[4];
            pf[0] = exp2_h2(fmaf(S[2 * t][0], L2E, -nl0),
                            fmaf(S[2 * t][1], L2E, -nl0));
            pf[1] = exp2_h2(fmaf(S[2 * t][2], L2E, -nl1),
                            fmaf(S[2 * t][3], L2E, -nl1));
            pf[2] = exp2_h2(fmaf(S[2 * t + 1][0], L2E, -nl0),
                            fmaf(S[2 * t + 1][1], L2E, -nl0));
            pf[3] = exp2_h2(fmaf(S[2 * t + 1][2], L2E, -nl1),
                            fmaf(S[2 * t + 1][3], L2E, -nl1));
            hs0 = __hadd2(hs0, __hadd2(*(__half2*)&pf[0], *(__half2*)&pf[2]));
            hs1 = __hadd2(hs1, __hadd2(*(__half2*)&pf[1], *(__half2*)&pf[3]));
            #pragma unroll
            for (int dt = 0; dt < 8; dt += 2) {
                uint32_t vf[4];
                int vrow = t * 16 + (g8 & 1) * 8 + (lane & 7);
                int vcol = (dt + (g8 >> 1)) * 8;
                ldmx4t(vf, sbase + F_V * 2 + (uint32_t)((vrow * RS2 + vcol) * 2));
                mmaf16(O[dt], pf, vf);
                mmaf16(O[dt + 1], pf, vf + 2);
            }
        }

        float rs0 = __low2float(hs0) + __high2float(hs0);
        float rs1 = __low2float(hs1) + __high2float(hs1);
        rs0 += __shfl_xor_sync(0xffffffffu, rs0, 1);
        rs0 += __shfl_xor_sync(0xffffffffu, rs0, 2);
        rs1 += __shfl_xor_sync(0xffffffffu, rs1, 1);
        rs1 += __shfl_xor_sync(0xffffffffu, rs1, 2);
        l0 = l0 * sc0 + rs0;
        l1 = l1 * sc1 + rs1;
        mr0 = mn0; mr1 = mn1;
    }

    // ---- epilogue: /l and /32 quirk, fp16 store ----
    float inv0 = 1.f / (l0 * 32.f), inv1 = 1.f / (l1 * 32.f);
    int r = lane >> 2, c2 = (lane & 3) * 2;
    int q = q0 + wid * 16 + r;
    #pragma unroll
    for (int dt = 0; dt < 8; dt++) {
        int col = h * 64 + dt * 8 + c2;
        size_t off0 = (size_t)(b * N_ + q) * D_ + col;
        size_t off1 = (size_t)(b * N_ + q + 8) * D_ + col;
        *(uint32_t*)(oh + off0) = pack_h2(O[dt][0] * inv0, O[dt][1] * inv0);
        *(uint32_t*)(oh + off1) = pack_h2(O[dt][2] * inv1, O[dt][3] * inv1);
    }
}

// ===================================================================
extern "C" void kernel_launch(void* const* d_in, const int* in_sizes, int n_in,
                              void* d_out, int out_size)
{
    const float* hidden = (const float*)d_in[0];
    const float* w      = (const float*)d_in[1];
    const float* ln_g   = (const float*)d_in[2];
    const float* ln_b   = (const float*)d_in[3];
    const float* Wg     = (const float*)d_in[4];
    const float* bg     = (const float*)d_in[5];
    const float* Wb     = (const float*)d_in[6];
    const float* bb     = (const float*)d_in[7];
    const float* Wqkv   = (const float*)d_in[8];
    const float* bqkv   = (const float*)d_in[9];
    const float* Wp     = (const float*)d_in[10];
    const float* bp     = (const float*)d_in[11];
    float* out = (float*)d_out;

    float *p_h1, *p_bqkv;
    __half *p_qkvh, *p_ah, *p_bh;
    cudaGetSymbolAddress((void**)&p_qkvh, g_qkvh);
    cudaGetSymbolAddress((void**)&p_h1, g_h1);
    cudaGetSymbolAddress((void**)&p_bqkv, g_bqkv);
    cudaGetSymbolAddress((void**)&p_ah, g_Ah);
    cudaGetSymbolAddress((void**)&p_bh, g_Bh);

    cudaFuncSetAttribute(flash_tc,
                         cudaFuncAttributeMaxDynamicSharedMemorySize, FLASH_SMEM);
    cudaFuncSetAttribute(gemm_mma,
                         cudaFuncAttributeMaxDynamicSharedMemorySize, GEMM_SMEM);

    // 1) gamma/beta + permuted qkv bias
    gamma_beta_kernel<<<32, 256>>>(w, Wg, bg, Wb, bb);
    permute_bias<<<12, 256>>>(bqkv);

    // 2) h = sln(hidden) -> fp16
    sln_kernel<<<M_, 256>>>(hidden, ln_g, ln_b, nullptr, p_ah, 0);

    // 3) qkv = h @ Wqkv^T + bqkv (permuted cols) -> fp16
    cvt_half_permW<<<(QKV_ * D_) / 2048, 256>>>(Wqkv, p_bh);
    gemm_mma<<<dim3(QKV_ / 128, M_ / 128), 256, GEMM_SMEM>>>(
        p_ah, p_bh, p_bqkv, nullptr, nullptr, p_qkvh, M_, QKV_, D_);

    // 4) attention -> fp16 attn output in g_Ah
    flash_tc<<<dim3(N_ / 128, B_ * H_), 256, FLASH_SMEM>>>(p_ah);

    // 5) h1 = attn @ Wp^T + bp + hidden (fp32 out)
    cvt_half<<<(D_ * D_) / 2048, 256>>>(Wp, p_bh);
    gemm_mma<<<dim3(D_ / 128, M_ / 128), 256, GEMM_SMEM>>>(
        p_ah, p_bh, bp, hidden, p_h1, nullptr, M_, D_, D_);

    // 6) out = sln(h1) + h1
    sln_kernel<<<M_, 256>>>(p_h1, ln_g, ln_b, out, nullptr, 1);
}